// round 9
// baseline (speedup 1.0000x reference)
#include <cuda_runtime.h>
#include <cstdint>

// Dims (fixed): B=8, N=4096 -> M=32768; D=1024; E=512; C=4096
#define M_ROWS 32768
#define D_DIM  1024
#define E_DIM  512
#define C_DIM  4096

#define X_ELEMS  (M_ROWS * D_DIM)   // 33554432
#define RP_ELEMS (D_DIM * E_DIM)    // 524288
#define CB_ELEMS (C_DIM * E_DIM)    // 2097152

// Scratch (device globals: allocation-free per harness rules).
__device__ __align__(256) float g_projT[(size_t)E_DIM * M_ROWS];  // proj^T [E][M], 64 MB
__device__ __align__(256) float g_cbT[(size_t)E_DIM * C_DIM];     // cb^T  [E][C],  8 MB
__device__ __align__(256) float g_cbinv[C_DIM];                   // 16 KB

// ---------- packed f32x2 helpers ----------
__device__ __forceinline__ unsigned long long ffma2(unsigned long long a,
                                                    unsigned long long b,
                                                    unsigned long long c) {
    unsigned long long d;
    asm("fma.rn.f32x2 %0, %1, %2, %3;" : "=l"(d) : "l"(a), "l"(b), "l"(c));
    return d;
}
__device__ __forceinline__ void upk2(unsigned long long v, float& x, float& y) {
    asm("mov.b64 {%0, %1}, %2;" : "=f"(x), "=f"(y) : "l"(v));
}
// 128B-block XOR swizzle on 16B chunks: conflict-free strided LDS/STS.128.
__device__ __host__ __forceinline__ constexpr int swz(int c) { return c ^ ((c >> 3) & 7); }

// ---------- kernel 0a: codebook row inverse L2 norms (warp per row) ----------
__global__ void codebook_invnorm(const float* __restrict__ cb) {
    const int row  = blockIdx.x * 8 + (threadIdx.x >> 5);
    const int lane = threadIdx.x & 31;
    if (row >= C_DIM) return;
    const float* v = cb + (size_t)row * E_DIM;
    float s = 0.f;
    #pragma unroll
    for (int q = 0; q < E_DIM / 32; q++) {
        float t = v[lane + q * 32];
        s += t * t;
    }
    #pragma unroll
    for (int o = 16; o > 0; o >>= 1) s += __shfl_xor_sync(0xffffffffu, s, o);
    if (lane == 0) g_cbinv[row] = 1.f / fmaxf(sqrtf(s), 1e-12f);
}

// ---------- kernel 0b: transpose codebook [C,E] -> g_cbT [E,C] ----------
__global__ void cb_transpose(const float* __restrict__ cb) {
    __shared__ float t[32][33];
    const int tx = threadIdx.x, ty = threadIdx.y;       // 32 x 8
    const int c0 = blockIdx.x * 32, e0 = blockIdx.y * 32;
    #pragma unroll
    for (int i = 0; i < 4; i++)
        t[ty + 8 * i][tx] = cb[(size_t)(c0 + ty + 8 * i) * E_DIM + e0 + tx];
    __syncthreads();
    #pragma unroll
    for (int i = 0; i < 4; i++)
        g_cbT[(size_t)(e0 + ty + 8 * i) * C_DIM + c0 + tx] = t[tx][ty + 8 * i];
}

// ---------- kernel 1: proj^T = (x @ RP)^T  (unchanged from R8, known-good) ----------
__global__ __launch_bounds__(256) void proj_gemm(const float* __restrict__ X,
                                                 const float* __restrict__ RP) {
    __shared__ float As[2][16][128];
    __shared__ float Bs[2][16][256];
    const int tid = threadIdx.x;
    const int tx = tid & 15;
    const int ty = tid >> 4;
    const int row0 = blockIdx.y * 128;
    const int col0 = blockIdx.x * 128;

    const int o0 = 4 * swz(2 * tx), o1 = 4 * swz(2 * tx + 1);
    const int o2 = 4 * swz(32 + 2 * tx), o3 = 4 * swz(33 + 2 * tx);

    unsigned long long acc[4][8];
    #pragma unroll
    for (int r = 0; r < 4; r++)
        #pragma unroll
        for (int j = 0; j < 8; j++) acc[r][j] = 0ull;

    auto ldA = [&](int r, int kt) {
        int idx = tid + 256 * r, m = idx >> 2, k4 = (idx & 3) * 4;
        return *(const float4*)(X + (size_t)(row0 + m) * D_DIM + kt + k4);
    };
    auto stA = [&](int b, int r, float4 v) {
        int idx = tid + 256 * r, m = idx >> 2, k4 = (idx & 3) * 4;
        As[b][k4 + 0][m] = v.x; As[b][k4 + 1][m] = v.y;
        As[b][k4 + 2][m] = v.z; As[b][k4 + 3][m] = v.w;
    };
    auto ldB = [&](int r, int kt) {
        int idx = tid + 256 * r, n4 = (idx & 31) * 4, kb = idx >> 5;
        return *(const float4*)(RP + (size_t)(kt + kb) * E_DIM + col0 + n4);
    };
    auto stB = [&](int b, int r, float4 v) {
        int idx = tid + 256 * r, cB = (idx & 31) * 2, kb = idx >> 5;
        float* br = Bs[b][kb];
        *(float4*)(br + 4 * swz(cB))     = make_float4(v.x, v.x, v.y, v.y);
        *(float4*)(br + 4 * swz(cB + 1)) = make_float4(v.z, v.z, v.w, v.w);
    };

    stA(0, 0, ldA(0, 0)); stA(0, 1, ldA(1, 0));
    stB(0, 0, ldB(0, 0)); stB(0, 1, ldB(1, 0));
    __syncthreads();

    const int STEPS = D_DIM / 16;
    for (int s = 0; s < STEPS; s++) {
        const int buf = s & 1;
        const bool pf = (s + 1 < STEPS);
        float4 pa0, pa1, pb0, pb1;
        if (pf) {
            int kt1 = (s + 1) * 16;
            pa0 = ldA(0, kt1); pa1 = ldA(1, kt1);
            pb0 = ldB(0, kt1); pb1 = ldB(1, kt1);
        }
        #pragma unroll
        for (int k = 0; k < 16; k++) {
            ulonglong2 apA = *(const ulonglong2*)&As[buf][k][4 * ty];
            ulonglong2 apB = *(const ulonglong2*)&As[buf][k][64 + 4 * ty];
            const float* br = Bs[buf][k];
            ulonglong2 b0 = *(const ulonglong2*)(br + o0);
            ulonglong2 b1 = *(const ulonglong2*)(br + o1);
            ulonglong2 b2 = *(const ulonglong2*)(br + o2);
            ulonglong2 b3 = *(const ulonglong2*)(br + o3);
            unsigned long long av[4] = { apA.x, apA.y, apB.x, apB.y };
            unsigned long long bb[8] = { b0.x, b0.y, b1.x, b1.y,
                                         b2.x, b2.y, b3.x, b3.y };
            #pragma unroll
            for (int r = 0; r < 4; r++)
                #pragma unroll
                for (int j = 0; j < 8; j++)
                    acc[r][j] = ffma2(av[r], bb[j], acc[r][j]);
        }
        if (pf) {
            int nb = buf ^ 1;
            stA(nb, 0, pa0); stA(nb, 1, pa1);
            stB(nb, 0, pb0); stB(nb, 1, pb1);
        }
        __syncthreads();
    }

    #pragma unroll
    for (int j = 0; j < 8; j++) {
        const int col = col0 + ((j < 4) ? (4 * tx + j) : (60 + 4 * tx + j));
        float v0, v1, v2, v3;
        upk2(acc[0][j], v0, v1); upk2(acc[1][j], v2, v3);
        *(float4*)(g_projT + (size_t)col * M_ROWS + row0 + 4 * ty)
            = make_float4(v0, v1, v2, v3);
        upk2(acc[2][j], v0, v1); upk2(acc[3][j], v2, v3);
        *(float4*)(g_projT + (size_t)col * M_ROWS + row0 + 64 + 4 * ty)
            = make_float4(v0, v1, v2, v3);
    }
}

// ---------- kernel 2: fused scores + argmax (512 threads, A-dup layout) ----------
// Tile 128 rows x 128 cols, BK=8, double-buffered. Per thread: 4 rows x 8 cols.
// A (proj rows) duplicated+swizzled in smem -> (a,a) pairs, broadcast reads.
// B (codebook) natural -> (b0,b1) pairs straight from LDS.128.
// acc[i][jp] = rows 4ty+i, col-pairs. Bitwise-identical k-order to R8.
__global__ __launch_bounds__(512) void score_argmax(float* __restrict__ out) {
    __shared__ float As[2][8][256];   // dup rows, swizzled 16B chunks
    __shared__ float Bs[2][8][128];   // natural cols
    const int tid = threadIdx.x;
    const int tx = tid & 15;          // col group
    const int ty = tid >> 4;          // row group 0..31
    const int row0 = blockIdx.x * 128;

    const int oa0 = 4 * swz(2 * ty), oa1 = 4 * swz(2 * ty + 1);
    const int lane6 = tid & 63;       // fill lane
    const int kfill = tid >> 6;       // fill k-row 0..7
    const int sa0 = 4 * swz(lane6);   // dup-store offset

    unsigned long long acc[4][4];
    #pragma unroll
    for (int i = 0; i < 4; i++)
        #pragma unroll
        for (int jp = 0; jp < 4; jp++) acc[i][jp] = 0ull;

    float best[4];
    int   besti[4];
    #pragma unroll
    for (int i = 0; i < 4; i++) { best[i] = -3.402823466e38f; besti[i] = 0; }

    auto ldA = [&](int kt) {   // one float2 over M per thread
        return *(const float2*)(g_projT + (size_t)(kt + kfill) * M_ROWS + row0 + lane6 * 2);
    };
    auto stA = [&](int b, float2 v) {   // dup rows (v.x,v.x,v.y,v.y), swizzled
        *(float4*)&As[b][kfill][sa0] = make_float4(v.x, v.x, v.y, v.y);
    };
    auto ldB = [&](int ct, int kt) {
        return *(const float2*)(g_cbT + (size_t)(kt + kfill) * C_DIM + ct + lane6 * 2);
    };
    auto stB = [&](int b, float2 v) {
        *(float2*)&Bs[b][kfill][lane6 * 2] = v;
    };

    stA(0, ldA(0));
    stB(0, ldB(0, 0));
    __syncthreads();

    const int TOT = 32 * 64;   // 32 C-tiles x 64 K-tiles (BK=8)
    for (int s = 0; s < TOT; s++) {
        const int buf = s & 1;
        const bool pf = (s + 1 < TOT);
        float2 pa, pb;
        if (pf) {
            int kt1 = ((s + 1) & 63) * 8;
            int ct1 = ((s + 1) >> 6) * 128;
            pa = ldA(kt1);
            pb = ldB(ct1, kt1);
        }
        #pragma unroll
        for (int k = 0; k < 8; k++) {
            const float* ar = As[buf][k];
            ulonglong2 a01 = *(const ulonglong2*)(ar + oa0);   // rows 4ty,4ty+1 dup
            ulonglong2 a23 = *(const ulonglong2*)(ar + oa1);   // rows 4ty+2,4ty+3 dup
            const float* br = Bs[buf][k];
            ulonglong2 bl = *(const ulonglong2*)(br + 4 * tx);        // cols 4tx..4tx+3
            ulonglong2 bh = *(const ulonglong2*)(br + 64 + 4 * tx);   // cols 64+4tx..+3
            unsigned long long av[4] = { a01.x, a01.y, a23.x, a23.y };
            unsigned long long bb[4] = { bl.x, bl.y, bh.x, bh.y };
            #pragma unroll
            for (int i = 0; i < 4; i++)
                #pragma unroll
                for (int jp = 0; jp < 4; jp++)
                    acc[i][jp] = ffma2(av[i], bb[jp], acc[i][jp]);
        }
        if ((s & 63) == 63) {
            // end of a C-tile: argmax update (ascending c within thread ->
            // strict > keeps FIRST max, matching jnp.argmax), reset acc.
            const int ctb = (s >> 6) * 128;
            #pragma unroll
            for (int jp = 0; jp < 4; jp++) {
                const int c = ctb + ((jp < 2) ? (4 * tx + 2 * jp) : (64 + 4 * tx + 2 * (jp - 2)));
                const float2 ivn = *(const float2*)(g_cbinv + c);
                #pragma unroll
                for (int i = 0; i < 4; i++) {
                    float s0, s1;
                    upk2(acc[i][jp], s0, s1);
                    s0 *= ivn.x; s1 *= ivn.y;
                    if (s0 > best[i]) { best[i] = s0; besti[i] = c; }
                    if (s1 > best[i]) { best[i] = s1; besti[i] = c + 1; }
                    acc[i][jp] = 0ull;
                }
            }
        }
        if (pf) {
            int nb = buf ^ 1;
            stA(nb, pa);
            stB(nb, pb);
        }
        __syncthreads();
    }

    // reduce over the 16 tx lanes (half-warp xor shuffles).
    #pragma unroll
    for (int i = 0; i < 4; i++) {
        float sv = best[i];
        int   ix = besti[i];
        #pragma unroll
        for (int off = 1; off <= 8; off <<= 1) {
            float ps = __shfl_xor_sync(0xffffffffu, sv, off);
            int   pi = __shfl_xor_sync(0xffffffffu, ix, off);
            if (ps > sv || (ps == sv && pi < ix)) { sv = ps; ix = pi; }
        }
        if (tx == 0)
            out[row0 + 4 * ty + i] = (float)ix;   // harness reads float32
    }
}

extern "C" void kernel_launch(void* const* d_in, const int* in_sizes, int n_in,
                              void* d_out, int out_size) {
    const float* x  = nullptr;
    const float* rp = nullptr;
    const float* cb = nullptr;
    for (int i = 0; i < n_in; i++) {
        if (in_sizes[i] == X_ELEMS)       x  = (const float*)d_in[i];
        else if (in_sizes[i] == RP_ELEMS) rp = (const float*)d_in[i];
        else if (in_sizes[i] == CB_ELEMS) cb = (const float*)d_in[i];
    }
    if (!x || !rp || !cb) {
        x  = (const float*)d_in[0];
        rp = (const float*)d_in[1];
        cb = (const float*)d_in[2];
    }
    float* out = (float*)d_out;  // harness reads output as float32

    codebook_invnorm<<<C_DIM / 8, 256>>>(cb);
    cb_transpose<<<dim3(C_DIM / 32, E_DIM / 32), dim3(32, 8)>>>(cb);
    proj_gemm<<<dim3(E_DIM / 128, M_ROWS / 128), 256>>>(x, rp);
    score_argmax<<<M_ROWS / 128, 512>>>(out);
}

// round 10
// speedup vs baseline: 1.3660x; 1.3660x over previous
#include <cuda_runtime.h>
#include <cstdint>

// Dims (fixed): B=8, N=4096 -> M=32768; D=1024; E=512; C=4096
#define M_ROWS 32768
#define D_DIM  1024
#define E_DIM  512
#define C_DIM  4096

#define X_ELEMS  (M_ROWS * D_DIM)   // 33554432
#define RP_ELEMS (D_DIM * E_DIM)    // 524288
#define CB_ELEMS (C_DIM * E_DIM)    // 2097152

// Scratch (device globals: allocation-free per harness rules).
__device__ __align__(256) float g_projT[(size_t)E_DIM * M_ROWS];  // proj^T [E][M], 64 MB
__device__ __align__(256) float g_cbT[(size_t)E_DIM * C_DIM];     // cb^T  [E][C],  8 MB
__device__ __align__(256) float g_cbinv[C_DIM];                   // 16 KB

// ---------- packed f32x2 helpers ----------
__device__ __forceinline__ unsigned long long ffma2(unsigned long long a,
                                                    unsigned long long b,
                                                    unsigned long long c) {
    unsigned long long d;
    asm("fma.rn.f32x2 %0, %1, %2, %3;" : "=l"(d) : "l"(a), "l"(b), "l"(c));
    return d;
}
__device__ __forceinline__ void upk2(unsigned long long v, float& x, float& y) {
    asm("mov.b64 {%0, %1}, %2;" : "=f"(x), "=f"(y) : "l"(v));
}
// 128B-block XOR swizzle on 16B chunks: conflict-free strided LDS/STS.128.
__device__ __host__ __forceinline__ constexpr int swz(int c) { return c ^ ((c >> 3) & 7); }

// ---------- kernel 0a: codebook row inverse L2 norms (warp per row) ----------
__global__ void codebook_invnorm(const float* __restrict__ cb) {
    const int row  = blockIdx.x * 8 + (threadIdx.x >> 5);
    const int lane = threadIdx.x & 31;
    if (row >= C_DIM) return;
    const float* v = cb + (size_t)row * E_DIM;
    float s = 0.f;
    #pragma unroll
    for (int q = 0; q < E_DIM / 32; q++) {
        float t = v[lane + q * 32];
        s += t * t;
    }
    #pragma unroll
    for (int o = 16; o > 0; o >>= 1) s += __shfl_xor_sync(0xffffffffu, s, o);
    if (lane == 0) g_cbinv[row] = 1.f / fmaxf(sqrtf(s), 1e-12f);
}

// ---------- kernel 0b: transpose codebook [C,E] -> g_cbT [E,C] ----------
__global__ void cb_transpose(const float* __restrict__ cb) {
    __shared__ float t[32][33];
    const int tx = threadIdx.x, ty = threadIdx.y;       // 32 x 8
    const int c0 = blockIdx.x * 32, e0 = blockIdx.y * 32;
    #pragma unroll
    for (int i = 0; i < 4; i++)
        t[ty + 8 * i][tx] = cb[(size_t)(c0 + ty + 8 * i) * E_DIM + e0 + tx];
    __syncthreads();
    #pragma unroll
    for (int i = 0; i < 4; i++)
        g_cbT[(size_t)(e0 + ty + 8 * i) * C_DIM + c0 + tx] = t[tx][ty + 8 * i];
}

// ---------- kernel 1: proj^T = (x @ RP)^T  (R8 version, known-good) ----------
__global__ __launch_bounds__(256) void proj_gemm(const float* __restrict__ X,
                                                 const float* __restrict__ RP) {
    __shared__ float As[2][16][128];
    __shared__ float Bs[2][16][256];
    const int tid = threadIdx.x;
    const int tx = tid & 15;
    const int ty = tid >> 4;
    const int row0 = blockIdx.y * 128;
    const int col0 = blockIdx.x * 128;

    const int o0 = 4 * swz(2 * tx), o1 = 4 * swz(2 * tx + 1);
    const int o2 = 4 * swz(32 + 2 * tx), o3 = 4 * swz(33 + 2 * tx);

    unsigned long long acc[4][8];
    #pragma unroll
    for (int r = 0; r < 4; r++)
        #pragma unroll
        for (int j = 0; j < 8; j++) acc[r][j] = 0ull;

    auto ldA = [&](int r, int kt) {
        int idx = tid + 256 * r, m = idx >> 2, k4 = (idx & 3) * 4;
        return *(const float4*)(X + (size_t)(row0 + m) * D_DIM + kt + k4);
    };
    auto stA = [&](int b, int r, float4 v) {
        int idx = tid + 256 * r, m = idx >> 2, k4 = (idx & 3) * 4;
        As[b][k4 + 0][m] = v.x; As[b][k4 + 1][m] = v.y;
        As[b][k4 + 2][m] = v.z; As[b][k4 + 3][m] = v.w;
    };
    auto ldB = [&](int r, int kt) {
        int idx = tid + 256 * r, n4 = (idx & 31) * 4, kb = idx >> 5;
        return *(const float4*)(RP + (size_t)(kt + kb) * E_DIM + col0 + n4);
    };
    auto stB = [&](int b, int r, float4 v) {
        int idx = tid + 256 * r, cB = (idx & 31) * 2, kb = idx >> 5;
        float* br = Bs[b][kb];
        *(float4*)(br + 4 * swz(cB))     = make_float4(v.x, v.x, v.y, v.y);
        *(float4*)(br + 4 * swz(cB + 1)) = make_float4(v.z, v.z, v.w, v.w);
    };

    stA(0, 0, ldA(0, 0)); stA(0, 1, ldA(1, 0));
    stB(0, 0, ldB(0, 0)); stB(0, 1, ldB(1, 0));
    __syncthreads();

    const int STEPS = D_DIM / 16;
    for (int s = 0; s < STEPS; s++) {
        const int buf = s & 1;
        const bool pf = (s + 1 < STEPS);
        float4 pa0, pa1, pb0, pb1;
        if (pf) {
            int kt1 = (s + 1) * 16;
            pa0 = ldA(0, kt1); pa1 = ldA(1, kt1);
            pb0 = ldB(0, kt1); pb1 = ldB(1, kt1);
        }
        #pragma unroll
        for (int k = 0; k < 16; k++) {
            ulonglong2 apA = *(const ulonglong2*)&As[buf][k][4 * ty];
            ulonglong2 apB = *(const ulonglong2*)&As[buf][k][64 + 4 * ty];
            const float* br = Bs[buf][k];
            ulonglong2 b0 = *(const ulonglong2*)(br + o0);
            ulonglong2 b1 = *(const ulonglong2*)(br + o1);
            ulonglong2 b2 = *(const ulonglong2*)(br + o2);
            ulonglong2 b3 = *(const ulonglong2*)(br + o3);
            unsigned long long av[4] = { apA.x, apA.y, apB.x, apB.y };
            unsigned long long bb[8] = { b0.x, b0.y, b1.x, b1.y,
                                         b2.x, b2.y, b3.x, b3.y };
            #pragma unroll
            for (int r = 0; r < 4; r++)
                #pragma unroll
                for (int j = 0; j < 8; j++)
                    acc[r][j] = ffma2(av[r], bb[j], acc[r][j]);
        }
        if (pf) {
            int nb = buf ^ 1;
            stA(nb, 0, pa0); stA(nb, 1, pa1);
            stB(nb, 0, pb0); stB(nb, 1, pb1);
        }
        __syncthreads();
    }

    #pragma unroll
    for (int j = 0; j < 8; j++) {
        const int col = col0 + ((j < 4) ? (4 * tx + j) : (60 + 4 * tx + j));
        float v0, v1, v2, v3;
        upk2(acc[0][j], v0, v1); upk2(acc[1][j], v2, v3);
        *(float4*)(g_projT + (size_t)col * M_ROWS + row0 + 4 * ty)
            = make_float4(v0, v1, v2, v3);
        upk2(acc[2][j], v0, v1); upk2(acc[3][j], v2, v3);
        *(float4*)(g_projT + (size_t)col * M_ROWS + row0 + 64 + 4 * ty)
            = make_float4(v0, v1, v2, v3);
    }
}

// ---------- kernel 2: fused scores + argmax ----------
// 512 threads, tile 256 rows x 128 cols, BK=16, double-buffered.
// Inner loop identical op mix to R8 (6 LDS.128 + 32 FFMA2 per k-step):
// A natural (broadcast reads), B duplicated+swizzled. 4 warps/SMSP; grid=128
// = single wave on 148 SMs. Bitwise-identical k-order to R8 -> rel_err 0.
__global__ __launch_bounds__(512) void score_argmax(float* __restrict__ out) {
    __shared__ float As[2][16][256];   // [k][m] natural, 16 KB/stage
    __shared__ float Bs[2][16][256];   // [k][dup-col] swizzled, 16 KB/stage
    const int tid = threadIdx.x;
    const int tx = tid & 15;           // col group
    const int ty = tid >> 4;           // row group 0..31
    const int row0 = blockIdx.x * 256;

    const int o0 = 4 * swz(2 * tx), o1 = 4 * swz(2 * tx + 1);
    const int o2 = 4 * swz(32 + 2 * tx), o3 = 4 * swz(33 + 2 * tx);

    unsigned long long acc[4][8];
    #pragma unroll
    for (int r = 0; r < 4; r++)
        #pragma unroll
        for (int j = 0; j < 8; j++) acc[r][j] = 0ull;

    float best[8];
    int   besti[8];
    #pragma unroll
    for (int i = 0; i < 8; i++) { best[i] = -3.402823466e38f; besti[i] = 0; }

    // A fill: 16 k-rows x 256 m = 1024 chunks of 16B; thread handles chunks
    // tid and tid+512 (coalesced within each k-row).
    auto ldA = [&](int r, int kt) {
        int c = tid + 512 * r, ka = c >> 6, m4 = (c & 63) * 4;
        return *(const float4*)(g_projT + (size_t)(kt + ka) * M_ROWS + row0 + m4);
    };
    auto stA = [&](int b, int r, float4 v) {
        int c = tid + 512 * r, ka = c >> 6, m4 = (c & 63) * 4;
        *(float4*)&As[b][ka][m4] = v;
    };
    // B fill: 16 k-rows x 128 cols from g_cbT; each thread loads one float4
    // and dup-stores two swizzled 16B chunks.
    auto ldB = [&](int ct, int kt) {
        int kb = tid >> 5, n4 = (tid & 31) * 4;
        return *(const float4*)(g_cbT + (size_t)(kt + kb) * C_DIM + ct + n4);
    };
    auto stB = [&](int b, float4 v) {
        int kb = tid >> 5, cB = (tid & 31) * 2;
        float* br = Bs[b][kb];
        *(float4*)(br + 4 * swz(cB))     = make_float4(v.x, v.x, v.y, v.y);
        *(float4*)(br + 4 * swz(cB + 1)) = make_float4(v.z, v.z, v.w, v.w);
    };

    stA(0, 0, ldA(0, 0)); stA(0, 1, ldA(1, 0));
    stB(0, ldB(0, 0));
    __syncthreads();

    const int TOT = 32 * 32;   // 32 C-tiles x 32 K-tiles (BK=16)
    for (int s = 0; s < TOT; s++) {
        const int buf = s & 1;
        const bool pf = (s + 1 < TOT);
        float4 pa0, pa1, pb;
        if (pf) {
            int kt1 = ((s + 1) & 31) * 16;
            int ct1 = ((s + 1) >> 5) * 128;
            pa0 = ldA(0, kt1); pa1 = ldA(1, kt1);
            pb  = ldB(ct1, kt1);
        }
        #pragma unroll
        for (int k = 0; k < 16; k++) {
            ulonglong2 apA = *(const ulonglong2*)&As[buf][k][4 * ty];         // rows 4ty..+3
            ulonglong2 apB = *(const ulonglong2*)&As[buf][k][128 + 4 * ty];   // rows 128+4ty..+3
            const float* br = Bs[buf][k];
            ulonglong2 b0 = *(const ulonglong2*)(br + o0);
            ulonglong2 b1 = *(const ulonglong2*)(br + o1);
            ulonglong2 b2 = *(const ulonglong2*)(br + o2);
            ulonglong2 b3 = *(const ulonglong2*)(br + o3);
            unsigned long long av[4] = { apA.x, apA.y, apB.x, apB.y };
            unsigned long long bb[8] = { b0.x, b0.y, b1.x, b1.y,
                                         b2.x, b2.y, b3.x, b3.y };
            #pragma unroll
            for (int r = 0; r < 4; r++)
                #pragma unroll
                for (int j = 0; j < 8; j++)
                    acc[r][j] = ffma2(av[r], bb[j], acc[r][j]);
        }
        if ((s & 31) == 31) {
            // end of a C-tile: argmax update (c ascending within thread ->
            // strict > keeps FIRST max, matching jnp.argmax), reset acc.
            const int ctb = (s >> 5) * 128;
            #pragma unroll
            for (int j = 0; j < 8; j++) {
                const int c = ctb + ((j < 4) ? (4 * tx + j) : (60 + 4 * tx + j));
                const float ivn = g_cbinv[c];
                #pragma unroll
                for (int r = 0; r < 4; r++) {
                    float s0, s1;
                    upk2(acc[r][j], s0, s1);
                    s0 *= ivn; s1 *= ivn;
                    if (s0 > best[r * 2 + 0]) { best[r * 2 + 0] = s0; besti[r * 2 + 0] = c; }
                    if (s1 > best[r * 2 + 1]) { best[r * 2 + 1] = s1; besti[r * 2 + 1] = c; }
                    acc[r][j] = 0ull;
                }
            }
        }
        if (pf) {
            int nb = buf ^ 1;
            stA(nb, 0, pa0); stA(nb, 1, pa1);
            stB(nb, pb);
        }
        __syncthreads();
    }

    // reduce over the 16 tx lanes (half-warp xor shuffles).
    // acc row mapping: e = rp*2+h -> row = 128*(rp>>1) + 4*ty + 2*(rp&1) + h
    #pragma unroll
    for (int e = 0; e < 8; e++) {
        float sv = best[e];
        int   ix = besti[e];
        #pragma unroll
        for (int off = 1; off <= 8; off <<= 1) {
            float ps = __shfl_xor_sync(0xffffffffu, sv, off);
            int   pi = __shfl_xor_sync(0xffffffffu, ix, off);
            if (ps > sv || (ps == sv && pi < ix)) { sv = ps; ix = pi; }
        }
        if (tx == 0) {
            const int rp = e >> 1;
            const int row = 128 * (rp >> 1) + 4 * ty + 2 * (rp & 1) + (e & 1);
            out[row0 + row] = (float)ix;   // harness reads output as float32
        }
    }
}

extern "C" void kernel_launch(void* const* d_in, const int* in_sizes, int n_in,
                              void* d_out, int out_size) {
    const float* x  = nullptr;
    const float* rp = nullptr;
    const float* cb = nullptr;
    for (int i = 0; i < n_in; i++) {
        if (in_sizes[i] == X_ELEMS)       x  = (const float*)d_in[i];
        else if (in_sizes[i] == RP_ELEMS) rp = (const float*)d_in[i];
        else if (in_sizes[i] == CB_ELEMS) cb = (const float*)d_in[i];
    }
    if (!x || !rp || !cb) {
        x  = (const float*)d_in[0];
        rp = (const float*)d_in[1];
        cb = (const float*)d_in[2];
    }
    float* out = (float*)d_out;  // harness reads output as float32

    codebook_invnorm<<<C_DIM / 8, 256>>>(cb);
    cb_transpose<<<dim3(C_DIM / 32, E_DIM / 32), dim3(32, 8)>>>(cb);
    proj_gemm<<<dim3(E_DIM / 128, M_ROWS / 128), 256>>>(x, rp);
    score_argmax<<<M_ROWS / 256, 512>>>(out);
}

// round 12
// speedup vs baseline: 2.5220x; 1.8463x over previous
#include <cuda_runtime.h>
#include <cuda_bf16.h>
#include <cstdint>

// Dims (fixed): B=8, N=4096 -> M=32768; D=1024; E=512; C=4096
#define M_ROWS 32768
#define D_DIM  1024
#define E_DIM  512
#define C_DIM  4096

#define X_ELEMS  (M_ROWS * D_DIM)   // 33554432
#define RP_ELEMS (D_DIM * E_DIM)    // 524288
#define CB_ELEMS (C_DIM * E_DIM)    // 2097152

// Scratch (device globals: allocation-free per harness rules).
__device__ __align__(256) float          g_projT[(size_t)E_DIM * M_ROWS];   // proj^T [E][M], 64 MB
__device__ __align__(256) float          g_cbT[(size_t)E_DIM * C_DIM];      // cb^T  [E][C],  8 MB
__device__ __align__(256) float          g_cbinv[C_DIM];                    // 16 KB
__device__ __align__(256) __nv_bfloat16  g_ps[(size_t)3 * M_ROWS * E_DIM];  // 96 MB proj splits [M][E]
__device__ __align__(256) __nv_bfloat16  g_cbs[(size_t)3 * C_DIM * E_DIM];  // 12 MB normalized-cb splits
__device__ int g_mma_done = 0;   // set by tensor path; fallback skips if 1

// Arch-specific gate: tcgen05 exists only on sm_103a-style targets.
#if defined(__CUDA_ARCH_FEAT_SM103_ALL)
#define HAS_TCGEN05 1
#elif defined(__CUDA_ARCH_SPECIFIC__)
#if __CUDA_ARCH_SPECIFIC__ == 1030
#define HAS_TCGEN05 1
#endif
#endif

// ---------- packed f32x2 helpers ----------
__device__ __forceinline__ unsigned long long ffma2(unsigned long long a,
                                                    unsigned long long b,
                                                    unsigned long long c) {
    unsigned long long d;
    asm("fma.rn.f32x2 %0, %1, %2, %3;" : "=l"(d) : "l"(a), "l"(b), "l"(c));
    return d;
}
__device__ __forceinline__ void upk2(unsigned long long v, float& x, float& y) {
    asm("mov.b64 {%0, %1}, %2;" : "=f"(x), "=f"(y) : "l"(v));
}
__device__ __host__ __forceinline__ constexpr int swz(int c) { return c ^ ((c >> 3) & 7); }

// fp32 -> 3 exact-residual bf16 splits
__device__ __forceinline__ void split3(float v, __nv_bfloat16& b1, __nv_bfloat16& b2, __nv_bfloat16& b3) {
    b1 = __float2bfloat16(v);
    float r = v - __bfloat162float(b1);
    b2 = __float2bfloat16(r);
    b3 = __float2bfloat16(r - __bfloat162float(b2));
}

// ========== prep kernels ==========
__global__ void codebook_invnorm(const float* __restrict__ cb) {
    const int row  = blockIdx.x * 8 + (threadIdx.x >> 5);
    const int lane = threadIdx.x & 31;
    if (row >= C_DIM) return;
    const float* v = cb + (size_t)row * E_DIM;
    float s = 0.f;
    #pragma unroll
    for (int q = 0; q < E_DIM / 32; q++) {
        float t = v[lane + q * 32];
        s += t * t;
    }
    #pragma unroll
    for (int o = 16; o > 0; o >>= 1) s += __shfl_xor_sync(0xffffffffu, s, o);
    if (lane == 0) g_cbinv[row] = 1.f / fmaxf(sqrtf(s), 1e-12f);
}

__global__ void cb_transpose(const float* __restrict__ cb) {
    __shared__ float t[32][33];
    const int tx = threadIdx.x, ty = threadIdx.y;       // 32 x 8
    const int c0 = blockIdx.x * 32, e0 = blockIdx.y * 32;
    #pragma unroll
    for (int i = 0; i < 4; i++)
        t[ty + 8 * i][tx] = cb[(size_t)(c0 + ty + 8 * i) * E_DIM + e0 + tx];
    __syncthreads();
    #pragma unroll
    for (int i = 0; i < 4; i++)
        g_cbT[(size_t)(e0 + ty + 8 * i) * C_DIM + c0 + tx] = t[tx][ty + 8 * i];
}

// normalize codebook rows + split to 3 bf16 (row-major [C][E])
__global__ void split_cbn(const float* __restrict__ cb) {
    __shared__ float red[4];
    const int c = blockIdx.x, t = threadIdx.x;   // 128 threads
    const float* v = cb + (size_t)c * E_DIM;
    float4 x = *(const float4*)(v + t * 4);
    float ss = x.x * x.x + x.y * x.y + x.z * x.z + x.w * x.w;
    #pragma unroll
    for (int o = 16; o > 0; o >>= 1) ss += __shfl_xor_sync(0xffffffffu, ss, o);
    if ((t & 31) == 0) red[t >> 5] = ss;
    __syncthreads();
    const float inv = 1.f / fmaxf(sqrtf(red[0] + red[1] + red[2] + red[3]), 1e-12f);
    float a[4] = { x.x * inv, x.y * inv, x.z * inv, x.w * inv };
    __nv_bfloat16 h[3][4];
    #pragma unroll
    for (int j = 0; j < 4; j++) split3(a[j], h[0][j], h[1][j], h[2][j]);
    const size_t base = (size_t)c * E_DIM + t * 4;
    #pragma unroll
    for (int s = 0; s < 3; s++)
        *(uint2*)(g_cbs + (size_t)s * C_DIM * E_DIM + base) = *(uint2*)h[s];
}

// transpose g_projT [E][M] -> bf16 splits g_ps (row-major [M][E])
__global__ void split_pT() {
    __shared__ float t[32][33];
    const int tx = threadIdx.x, ty = threadIdx.y;       // 32 x 8
    const int m0 = blockIdx.x * 32, e0 = blockIdx.y * 32;
    #pragma unroll
    for (int i = 0; i < 4; i++)
        t[ty + 8 * i][tx] = g_projT[(size_t)(e0 + ty + 8 * i) * M_ROWS + m0 + tx];
    __syncthreads();
    #pragma unroll
    for (int i = 0; i < 4; i++) {
        float v = t[tx][ty + 8 * i];
        __nv_bfloat16 b1, b2, b3;
        split3(v, b1, b2, b3);
        const size_t o = (size_t)(m0 + ty + 8 * i) * E_DIM + e0 + tx;
        g_ps[o] = b1;
        g_ps[(size_t)M_ROWS * E_DIM + o] = b2;
        g_ps[2 * (size_t)M_ROWS * E_DIM + o] = b3;
    }
}

// ========== kernel 1: proj^T = (x @ RP)^T  (R10 version, verified) ==========
__global__ __launch_bounds__(256) void proj_gemm(const float* __restrict__ X,
                                                 const float* __restrict__ RP) {
    __shared__ float As[2][16][128];
    __shared__ float Bs[2][16][256];
    const int tid = threadIdx.x;
    const int tx = tid & 15;
    const int ty = tid >> 4;
    const int row0 = blockIdx.y * 128;
    const int col0 = blockIdx.x * 128;

    const int o0 = 4 * swz(2 * tx), o1 = 4 * swz(2 * tx + 1);
    const int o2 = 4 * swz(32 + 2 * tx), o3 = 4 * swz(33 + 2 * tx);

    unsigned long long acc[4][8];
    #pragma unroll
    for (int r = 0; r < 4; r++)
        #pragma unroll
        for (int j = 0; j < 8; j++) acc[r][j] = 0ull;

    auto ldA = [&](int r, int kt) {
        int idx = tid + 256 * r, m = idx >> 2, k4 = (idx & 3) * 4;
        return *(const float4*)(X + (size_t)(row0 + m) * D_DIM + kt + k4);
    };
    auto stA = [&](int b, int r, float4 v) {
        int idx = tid + 256 * r, m = idx >> 2, k4 = (idx & 3) * 4;
        As[b][k4 + 0][m] = v.x; As[b][k4 + 1][m] = v.y;
        As[b][k4 + 2][m] = v.z; As[b][k4 + 3][m] = v.w;
    };
    auto ldB = [&](int r, int kt) {
        int idx = tid + 256 * r, n4 = (idx & 31) * 4, kb = idx >> 5;
        return *(const float4*)(RP + (size_t)(kt + kb) * E_DIM + col0 + n4);
    };
    auto stB = [&](int b, int r, float4 v) {
        int idx = tid + 256 * r, cB = (idx & 31) * 2, kb = idx >> 5;
        float* br = Bs[b][kb];
        *(float4*)(br + 4 * swz(cB))     = make_float4(v.x, v.x, v.y, v.y);
        *(float4*)(br + 4 * swz(cB + 1)) = make_float4(v.z, v.z, v.w, v.w);
    };

    stA(0, 0, ldA(0, 0)); stA(0, 1, ldA(1, 0));
    stB(0, 0, ldB(0, 0)); stB(0, 1, ldB(1, 0));
    __syncthreads();

    const int STEPS = D_DIM / 16;
    for (int s = 0; s < STEPS; s++) {
        const int buf = s & 1;
        const bool pf = (s + 1 < STEPS);
        float4 pa0, pa1, pb0, pb1;
        if (pf) {
            int kt1 = (s + 1) * 16;
            pa0 = ldA(0, kt1); pa1 = ldA(1, kt1);
            pb0 = ldB(0, kt1); pb1 = ldB(1, kt1);
        }
        #pragma unroll
        for (int k = 0; k < 16; k++) {
            ulonglong2 apA = *(const ulonglong2*)&As[buf][k][4 * ty];
            ulonglong2 apB = *(const ulonglong2*)&As[buf][k][64 + 4 * ty];
            const float* br = Bs[buf][k];
            ulonglong2 b0 = *(const ulonglong2*)(br + o0);
            ulonglong2 b1 = *(const ulonglong2*)(br + o1);
            ulonglong2 b2 = *(const ulonglong2*)(br + o2);
            ulonglong2 b3 = *(const ulonglong2*)(br + o3);
            unsigned long long av[4] = { apA.x, apA.y, apB.x, apB.y };
            unsigned long long bb[8] = { b0.x, b0.y, b1.x, b1.y,
                                         b2.x, b2.y, b3.x, b3.y };
            #pragma unroll
            for (int r = 0; r < 4; r++)
                #pragma unroll
                for (int j = 0; j < 8; j++)
                    acc[r][j] = ffma2(av[r], bb[j], acc[r][j]);
        }
        if (pf) {
            int nb = buf ^ 1;
            stA(nb, 0, pa0); stA(nb, 1, pa1);
            stB(nb, 0, pb0); stB(nb, 1, pb1);
        }
        __syncthreads();
    }

    #pragma unroll
    for (int j = 0; j < 8; j++) {
        const int col = col0 + ((j < 4) ? (4 * tx + j) : (60 + 4 * tx + j));
        float v0, v1, v2, v3;
        upk2(acc[0][j], v0, v1); upk2(acc[1][j], v2, v3);
        *(float4*)(g_projT + (size_t)col * M_ROWS + row0 + 4 * ty)
            = make_float4(v0, v1, v2, v3);
        upk2(acc[2][j], v0, v1); upk2(acc[3][j], v2, v3);
        *(float4*)(g_projT + (size_t)col * M_ROWS + row0 + 64 + 4 * ty)
            = make_float4(v0, v1, v2, v3);
    }
}

// ================= tcgen05 PTX (used only under HAS_TCGEN05) ================
__device__ __forceinline__ uint32_t elect_one_pred() {
    uint32_t pred;
    asm volatile("{\n\t.reg .pred p;\n\telect.sync _|p, 0xFFFFFFFF;\n\t"
                 "selp.b32 %0, 1, 0, p;\n\t}" : "=r"(pred));
    return pred;
}
__device__ __forceinline__ uint32_t smem_to_u32(const void* p) {
    uint32_t a;
    asm("{ .reg .u64 t; cvta.to.shared.u64 t, %1; cvt.u32.u64 %0, t; }" : "=r"(a) : "l"(p));
    return a;
}
#define SMEM_SWIZZLE_128B(off) ((off) ^ (((off) >> 3) & 0x70))
static constexpr unsigned long long SMEM_DESC_BASE_SW128 =
    (2ull << 61) | (1ull << 46) | (64ull << 32) | (1ull << 16);
#define MAKE_SMEM_DESC(a) (SMEM_DESC_BASE_SW128 | ((unsigned long long)((a) >> 4) & 0x3FFF))

#define MBARRIER_INIT(mb, n) \
    asm volatile("mbarrier.init.shared.b64 [%0], %1;" :: "r"((uint32_t)(mb)), "r"((uint32_t)(n)) : "memory")
#define MBARRIER_WAIT_PARITY(mb, par) do {                                        \
    uint32_t _m = (uint32_t)(mb), _p = (uint32_t)(par), _d;                        \
    asm volatile("{\n\t.reg .pred p;\n\t"                                          \
        "mbarrier.try_wait.parity.acquire.cta.shared::cta.b64 p, [%1], %2;\n\t"    \
        "selp.b32 %0, 1, 0, p;\n\t}" : "=r"(_d) : "r"(_m), "r"(_p) : "memory");    \
    if (!_d) {                                                                     \
        asm volatile("{\n\t.reg .pred P1;\n\tWL_%=:\n\t"                           \
            "mbarrier.try_wait.parity.acquire.cta.shared::cta.b64 P1, [%0], %1, 0x989680;\n\t" \
            "@P1 bra.uni WD_%=;\n\tbra.uni WL_%=;\n\tWD_%=:\n\t}"                  \
            :: "r"(_m), "r"(_p) : "memory");                                       \
    }                                                                              \
} while (0)

// idesc: dtype F32 (1<<4), a/b BF16 (1<<7|1<<10), N=128 (16<<17), M=128 (8<<24)
#define MMA_IDESC 0x8200490u

// ========== kernel 3: tensor-core score + argmax (arch-gated) ==========
#define SC_A0 0
#define SC_A1 (16 * 1024)
#define SC_B0 (32 * 1024)
#define SC_B1 (96 * 1024)
#define SC_CTRL (160 * 1024)       // +0 tmem ptr, +8 mbar0, +16 mbar1
#define SC_SMEM (160 * 1024 + 64)

__global__ __launch_bounds__(256) void score_mma(float* __restrict__ out) {
#ifdef HAS_TCGEN05
    extern __shared__ char smem[];
    const uint32_t sb = smem_to_u32(smem);
    const int tid = threadIdx.x;
    const int wid = tid >> 5;
    const int row0 = blockIdx.x * 128;

    if (wid == 0)
        asm volatile("tcgen05.alloc.cta_group::1.sync.aligned.shared::cta.b32 [%0], %1;"
                     :: "r"(sb + SC_CTRL), "r"(512u) : "memory");
    __syncthreads();
    uint32_t tmem;
    asm volatile("ld.shared.b32 %0, [%1];" : "=r"(tmem) : "r"(sb + SC_CTRL));
    if (tid == 0) {
        MBARRIER_INIT(sb + SC_CTRL + 8, 1);
        MBARRIER_INIT(sb + SC_CTRL + 16, 1);
    }
    __syncthreads();

    const int a_idx[6] = { 0, 0, 1, 0, 1, 2 };
    const int b_idx[6] = { 0, 1, 0, 2, 1, 0 };

    float best = -3.402823466e38f;
    int besti = 0;
    int ph[2] = { 0, 0 }, pend[2] = { 0, 0 };

    for (int g = 0; g < 8; g++) {
        for (int kc = 0; kc < 48; kc++) {
            const int gc = g * 48 + kc;
            const int buf = gc & 1;
            if (pend[buf]) {
                MBARRIER_WAIT_PARITY(sb + SC_CTRL + 8 + 8 * buf, ph[buf]);
                ph[buf] ^= 1; pend[buf] = 0;
            }
            const int t = kc >> 3, koff = (kc & 7) * 64;
            const __nv_bfloat16* Asrc = g_ps  + (size_t)a_idx[t] * M_ROWS * E_DIM;
            const __nv_bfloat16* Bsrc = g_cbs + (size_t)b_idx[t] * C_DIM  * E_DIM;
            const int aoff = buf ? SC_A1 : SC_A0;
            const int boff = buf ? SC_B1 : SC_B0;
            #pragma unroll
            for (int r = 0; r < 4; r++) {   // A: 128 rows x 64 bf16, SW128
                int ci = tid + 256 * r, m = ci >> 3, c8 = ci & 7;
                uint4 v = *(const uint4*)(Asrc + (size_t)(row0 + m) * E_DIM + koff + c8 * 8);
                *(uint4*)(smem + aoff + SMEM_SWIZZLE_128B(m * 128 + c8 * 16)) = v;
            }
            #pragma unroll
            for (int r = 0; r < 16; r++) {  // B: 512 codes x 64 bf16
                int ci = tid + 256 * r, n = ci >> 3, c8 = ci & 7;
                uint4 v = *(const uint4*)(Bsrc + (size_t)(g * 512 + n) * E_DIM + koff + c8 * 8);
                *(uint4*)(smem + boff + SMEM_SWIZZLE_128B(n * 128 + c8 * 16)) = v;
            }
            asm volatile("fence.proxy.async.shared::cta;" ::: "memory");
            __syncthreads();
            if (wid == 0 && elect_one_pred()) {
                unsigned long long ad = MAKE_SMEM_DESC(sb + aoff);
                #pragma unroll
                for (int nt = 0; nt < 4; nt++) {
                    unsigned long long bd = MAKE_SMEM_DESC(sb + boff + nt * 16384);
                    #pragma unroll
                    for (int ks = 0; ks < 4; ks++) {
                        uint32_t en = (kc != 0 || ks != 0) ? 1u : 0u;
                        asm volatile("{\n\t.reg .pred p;\n\tsetp.ne.u32 p, %4, 0;\n\t"
                            "tcgen05.mma.cta_group::1.kind::f16 [%0], %1, %2, %3, {%5, %5, %5, %5}, p;\n\t}"
                            :: "r"(tmem + nt * 128), "l"(ad + ks * 2), "l"(bd + ks * 2),
                               "r"(MMA_IDESC), "r"(en), "r"(0u) : "memory");
                    }
                }
                asm volatile("tcgen05.commit.cta_group::1.mbarrier::arrive::one.shared::cluster.b64 [%0];"
                             :: "r"(sb + SC_CTRL + 8 + 8 * buf) : "memory");
            }
            pend[buf] = 1;
        }
        #pragma unroll
        for (int b = 0; b < 2; b++)
            if (pend[b]) {
                MBARRIER_WAIT_PARITY(sb + SC_CTRL + 8 + 8 * b, ph[b]);
                ph[b] ^= 1; pend[b] = 0;
            }
        asm volatile("tcgen05.fence::after_thread_sync;" ::: "memory");
        if (tid < 128) {   // warps 0-3, lane -> row (row = tid)
            #pragma unroll
            for (int nt = 0; nt < 4; nt++) {
                #pragma unroll
                for (int b4 = 0; b4 < 4; b4++) {
                    uint32_t regs[32];
                    asm volatile("tcgen05.ld.sync.aligned.32x32b.x32.b32 "
                        "{%0, %1, %2, %3, %4, %5, %6, %7, %8, %9, %10, %11, %12, %13, %14, %15, "
                        " %16, %17, %18, %19, %20, %21, %22, %23, %24, %25, %26, %27, %28, %29, %30, %31}, [%32];"
                        : "=r"(regs[0]),  "=r"(regs[1]),  "=r"(regs[2]),  "=r"(regs[3]),
                          "=r"(regs[4]),  "=r"(regs[5]),  "=r"(regs[6]),  "=r"(regs[7]),
                          "=r"(regs[8]),  "=r"(regs[9]),  "=r"(regs[10]), "=r"(regs[11]),
                          "=r"(regs[12]), "=r"(regs[13]), "=r"(regs[14]), "=r"(regs[15]),
                          "=r"(regs[16]), "=r"(regs[17]), "=r"(regs[18]), "=r"(regs[19]),
                          "=r"(regs[20]), "=r"(regs[21]), "=r"(regs[22]), "=r"(regs[23]),
                          "=r"(regs[24]), "=r"(regs[25]), "=r"(regs[26]), "=r"(regs[27]),
                          "=r"(regs[28]), "=r"(regs[29]), "=r"(regs[30]), "=r"(regs[31])
                        : "r"(tmem + nt * 128 + b4 * 32));
                    asm volatile("tcgen05.wait::ld.sync.aligned;" ::: "memory");
                    const int cbase = g * 512 + nt * 128 + b4 * 32;
                    #pragma unroll
                    for (int c = 0; c < 32; c++) {
                        float s = __uint_as_float(regs[c]);
                        if (s > best) { best = s; besti = cbase + c; }
                    }
                }
            }
            asm volatile("tcgen05.fence::before_thread_sync;" ::: "memory");
        }
        __syncthreads();
    }

    if (tid < 128) out[row0 + tid] = (float)besti;   // harness reads float32
    __syncthreads();
    if (wid == 0)
        asm volatile("tcgen05.dealloc.cta_group::1.sync.aligned.b32 %0, %1;" :: "r"(tmem), "r"(512u));
    if (blockIdx.x == 0 && tid == 0) g_mma_done = 1;
#endif  // HAS_TCGEN05
}

// ========== fallback: R10 score_argmax verbatim (+early exit) ==========
__global__ __launch_bounds__(512) void score_fb(float* __restrict__ out) {
    if (g_mma_done) return;   // tensor path already produced the output
    __shared__ float As[2][16][256];
    __shared__ float Bs[2][16][256];
    const int tid = threadIdx.x;
    const int tx = tid & 15;
    const int ty = tid >> 4;
    const int row0 = blockIdx.x * 256;

    const int o0 = 4 * swz(2 * tx), o1 = 4 * swz(2 * tx + 1);
    const int o2 = 4 * swz(32 + 2 * tx), o3 = 4 * swz(33 + 2 * tx);

    unsigned long long acc[4][8];
    #pragma unroll
    for (int r = 0; r < 4; r++)
        #pragma unroll
        for (int j = 0; j < 8; j++) acc[r][j] = 0ull;

    float best[8];
    int   besti[8];
    #pragma unroll
    for (int i = 0; i < 8; i++) { best[i] = -3.402823466e38f; besti[i] = 0; }

    auto ldA = [&](int r, int kt) {
        int c = tid + 512 * r, ka = c >> 6, m4 = (c & 63) * 4;
        return *(const float4*)(g_projT + (size_t)(kt + ka) * M_ROWS + row0 + m4);
    };
    auto stA = [&](int b, int r, float4 v) {
        int c = tid + 512 * r, ka = c >> 6, m4 = (c & 63) * 4;
        *(float4*)&As[b][ka][m4] = v;
    };
    auto ldB = [&](int ct, int kt) {
        int kb = tid >> 5, n4 = (tid & 31) * 4;
        return *(const float4*)(g_cbT + (size_t)(kt + kb) * C_DIM + ct + n4);
    };
    auto stB = [&](int b, float4 v) {
        int kb = tid >> 5, cB = (tid & 31) * 2;
        float* br = Bs[b][kb];
        *(float4*)(br + 4 * swz(cB))     = make_float4(v.x, v.x, v.y, v.y);
        *(float4*)(br + 4 * swz(cB + 1)) = make_float4(v.z, v.z, v.w, v.w);
    };

    stA(0, 0, ldA(0, 0)); stA(0, 1, ldA(1, 0));
    stB(0, ldB(0, 0));
    __syncthreads();

    const int TOT = 32 * 32;
    for (int s = 0; s < TOT; s++) {
        const int buf = s & 1;
        const bool pf = (s + 1 < TOT);
        float4 pa0, pa1, pb;
        if (pf) {
            int kt1 = ((s + 1) & 31) * 16;
            int ct1 = ((s + 1) >> 5) * 128;
            pa0 = ldA(0, kt1); pa1 = ldA(1, kt1);
            pb  = ldB(ct1, kt1);
        }
        #pragma unroll
        for (int k = 0; k < 16; k++) {
            ulonglong2 apA = *(const ulonglong2*)&As[buf][k][4 * ty];
            ulonglong2 apB = *(const ulonglong2*)&As[buf][k][128 + 4 * ty];
            const float* br = Bs[buf][k];
            ulonglong2 b0 = *(const ulonglong2*)(br + o0);
            ulonglong2 b1 = *(const ulonglong2*)(br + o1);
            ulonglong2 b2 = *(const ulonglong2*)(br + o2);
            ulonglong2 b3 = *(const ulonglong2*)(br + o3);
            unsigned long long av[4] = { apA.x, apA.y, apB.x, apB.y };
            unsigned long long bb[8] = { b0.x, b0.y, b1.x, b1.y,
                                         b2.x, b2.y, b3.x, b3.y };
            #pragma unroll
            for (int r = 0; r < 4; r++)
                #pragma unroll
                for (int j = 0; j < 8; j++)
                    acc[r][j] = ffma2(av[r], bb[j], acc[r][j]);
        }
        if ((s & 31) == 31) {
            const int ctb = (s >> 5) * 128;
            #pragma unroll
            for (int j = 0; j < 8; j++) {
                const int c = ctb + ((j < 4) ? (4 * tx + j) : (60 + 4 * tx + j));
                const float ivn = g_cbinv[c];
                #pragma unroll
                for (int r = 0; r < 4; r++) {
                    float s0, s1;
                    upk2(acc[r][j], s0, s1);
                    s0 *= ivn; s1 *= ivn;
                    if (s0 > best[r * 2 + 0]) { best[r * 2 + 0] = s0; besti[r * 2 + 0] = c; }
                    if (s1 > best[r * 2 + 1]) { best[r * 2 + 1] = s1; besti[r * 2 + 1] = c; }
                    acc[r][j] = 0ull;
                }
            }
        }
        if (pf) {
            int nb = buf ^ 1;
            stA(nb, 0, pa0); stA(nb, 1, pa1);
            stB(nb, pb);
        }
        __syncthreads();
    }

    #pragma unroll
    for (int e = 0; e < 8; e++) {
        float sv = best[e];
        int   ix = besti[e];
        #pragma unroll
        for (int off = 1; off <= 8; off <<= 1) {
            float ps = __shfl_xor_sync(0xffffffffu, sv, off);
            int   pi = __shfl_xor_sync(0xffffffffu, ix, off);
            if (ps > sv || (ps == sv && pi < ix)) { sv = ps; ix = pi; }
        }
        if (tx == 0) {
            const int rp = e >> 1;
            const int row = 128 * (rp >> 1) + 4 * ty + 2 * (rp & 1) + (e & 1);
            out[row0 + row] = (float)ix;
        }
    }
}

extern "C" void kernel_launch(void* const* d_in, const int* in_sizes, int n_in,
                              void* d_out, int out_size) {
    const float* x  = nullptr;
    const float* rp = nullptr;
    const float* cb = nullptr;
    for (int i = 0; i < n_in; i++) {
        if (in_sizes[i] == X_ELEMS)       x  = (const float*)d_in[i];
        else if (in_sizes[i] == RP_ELEMS) rp = (const float*)d_in[i];
        else if (in_sizes[i] == CB_ELEMS) cb = (const float*)d_in[i];
    }
    if (!x || !rp || !cb) {
        x  = (const float*)d_in[0];
        rp = (const float*)d_in[1];
        cb = (const float*)d_in[2];
    }
    float* out = (float*)d_out;  // harness reads output as float32

    cudaFuncSetAttribute(score_mma, cudaFuncAttributeMaxDynamicSharedMemorySize, SC_SMEM);

    codebook_invnorm<<<C_DIM / 8, 256>>>(cb);
    cb_transpose<<<dim3(C_DIM / 32, E_DIM / 32), dim3(32, 8)>>>(cb);
    split_cbn<<<C_DIM, 128>>>(cb);
    proj_gemm<<<dim3(E_DIM / 128, M_ROWS / 128), 256>>>(x, rp);
    split_pT<<<dim3(M_ROWS / 32, E_DIM / 32), dim3(32, 8)>>>();
    score_mma<<<M_ROWS / 128, 256, SC_SMEM>>>(out);   // no-op on non-'a' targets
    score_fb<<<M_ROWS / 256, 512>>>(out);             // early-exits if MMA ran
}

// round 13
// speedup vs baseline: 2.6800x; 1.0626x over previous
#include <cuda_runtime.h>
#include <cuda_bf16.h>
#include <cstdint>

// Dims (fixed): B=8, N=4096 -> M=32768; D=1024; E=512; C=4096
#define M_ROWS 32768
#define D_DIM  1024
#define E_DIM  512
#define C_DIM  4096

#define X_ELEMS  (M_ROWS * D_DIM)   // 33554432
#define RP_ELEMS (D_DIM * E_DIM)    // 524288
#define CB_ELEMS (C_DIM * E_DIM)    // 2097152

// Scratch (device globals: allocation-free per harness rules).
__device__ __align__(256) __nv_bfloat16  g_xs[(size_t)3 * M_ROWS * D_DIM];  // 192 MB x splits [M][D]
__device__ __align__(256) __nv_bfloat16  g_rps[(size_t)3 * E_DIM * D_DIM]; //   3 MB RP^T splits [N][K]
__device__ __align__(256) __nv_bfloat16  g_ps[(size_t)3 * M_ROWS * E_DIM]; //  96 MB proj splits [M][E]
__device__ __align__(256) __nv_bfloat16  g_cbs[(size_t)3 * C_DIM * E_DIM]; //  12 MB normalized-cb splits

// Arch-specific gate: tcgen05 exists only on sm_103a-style targets.
#if defined(__CUDA_ARCH_FEAT_SM103_ALL)
#define HAS_TCGEN05 1
#elif defined(__CUDA_ARCH_SPECIFIC__)
#if __CUDA_ARCH_SPECIFIC__ == 1030
#define HAS_TCGEN05 1
#endif
#endif

// fp32 -> 3 exact-residual bf16 splits
__device__ __forceinline__ void split3(float v, __nv_bfloat16& b1, __nv_bfloat16& b2, __nv_bfloat16& b3) {
    b1 = __float2bfloat16(v);
    float r = v - __bfloat162float(b1);
    b2 = __float2bfloat16(r);
    b3 = __float2bfloat16(r - __bfloat162float(b2));
}

// ========== prep kernel: split x into 3 bf16 planes ==========
__global__ void split_x(const float* __restrict__ x) {
    const size_t i = ((size_t)blockIdx.x * blockDim.x + threadIdx.x) * 4;
    float4 v = *(const float4*)(x + i);
    float a[4] = { v.x, v.y, v.z, v.w };
    __nv_bfloat16 h[3][4];
    #pragma unroll
    for (int j = 0; j < 4; j++) split3(a[j], h[0][j], h[1][j], h[2][j]);
    #pragma unroll
    for (int s = 0; s < 3; s++)
        *(uint2*)(g_xs + (size_t)s * M_ROWS * D_DIM + i) = *(uint2*)h[s];
}

// ========== prep kernel: transpose RP [K,N] -> [N,K] + split ==========
__global__ void split_rpt(const float* __restrict__ rp) {
    __shared__ float t[32][33];
    const int tx = threadIdx.x, ty = threadIdx.y;       // 32 x 8
    const int n0 = blockIdx.x * 32, k0 = blockIdx.y * 32;
    #pragma unroll
    for (int i = 0; i < 4; i++)
        t[ty + 8 * i][tx] = rp[(size_t)(k0 + ty + 8 * i) * E_DIM + n0 + tx];
    __syncthreads();
    #pragma unroll
    for (int i = 0; i < 4; i++) {
        float v = t[tx][ty + 8 * i];
        __nv_bfloat16 b1, b2, b3;
        split3(v, b1, b2, b3);
        const size_t o = (size_t)(n0 + ty + 8 * i) * D_DIM + k0 + tx;
        g_rps[o] = b1;
        g_rps[(size_t)E_DIM * D_DIM + o] = b2;
        g_rps[2 * (size_t)E_DIM * D_DIM + o] = b3;
    }
}

// ========== prep kernel: normalize codebook rows + split to 3 bf16 ==========
__global__ void split_cbn(const float* __restrict__ cb) {
    __shared__ float red[4];
    const int c = blockIdx.x, t = threadIdx.x;   // 128 threads
    const float* v = cb + (size_t)c * E_DIM;
    float4 x = *(const float4*)(v + t * 4);
    float ss = x.x * x.x + x.y * x.y + x.z * x.z + x.w * x.w;
    #pragma unroll
    for (int o = 16; o > 0; o >>= 1) ss += __shfl_xor_sync(0xffffffffu, ss, o);
    if ((t & 31) == 0) red[t >> 5] = ss;
    __syncthreads();
    const float inv = 1.f / fmaxf(sqrtf(red[0] + red[1] + red[2] + red[3]), 1e-12f);
    float a[4] = { x.x * inv, x.y * inv, x.z * inv, x.w * inv };
    __nv_bfloat16 h[3][4];
    #pragma unroll
    for (int j = 0; j < 4; j++) split3(a[j], h[0][j], h[1][j], h[2][j]);
    const size_t base = (size_t)c * E_DIM + t * 4;
    #pragma unroll
    for (int s = 0; s < 3; s++)
        *(uint2*)(g_cbs + (size_t)s * C_DIM * E_DIM + base) = *(uint2*)h[s];
}

// ================= tcgen05 PTX helpers ================
__device__ __forceinline__ uint32_t elect_one_pred() {
    uint32_t pred;
    asm volatile("{\n\t.reg .pred p;\n\telect.sync _|p, 0xFFFFFFFF;\n\t"
                 "selp.b32 %0, 1, 0, p;\n\t}" : "=r"(pred));
    return pred;
}
__device__ __forceinline__ uint32_t smem_to_u32(const void* p) {
    uint32_t a;
    asm("{ .reg .u64 t; cvta.to.shared.u64 t, %1; cvt.u32.u64 %0, t; }" : "=r"(a) : "l"(p));
    return a;
}
#define SMEM_SWIZZLE_128B(off) ((off) ^ (((off) >> 3) & 0x70))
static constexpr unsigned long long SMEM_DESC_BASE_SW128 =
    (2ull << 61) | (1ull << 46) | (64ull << 32) | (1ull << 16);
#define MAKE_SMEM_DESC(a) (SMEM_DESC_BASE_SW128 | ((unsigned long long)((a) >> 4) & 0x3FFF))

#define MBARRIER_INIT(mb, n) \
    asm volatile("mbarrier.init.shared.b64 [%0], %1;" :: "r"((uint32_t)(mb)), "r"((uint32_t)(n)) : "memory")
#define MBARRIER_WAIT_PARITY(mb, par) do {                                        \
    uint32_t _m = (uint32_t)(mb), _p = (uint32_t)(par), _d;                        \
    asm volatile("{\n\t.reg .pred p;\n\t"                                          \
        "mbarrier.try_wait.parity.acquire.cta.shared::cta.b64 p, [%1], %2;\n\t"    \
        "selp.b32 %0, 1, 0, p;\n\t}" : "=r"(_d) : "r"(_m), "r"(_p) : "memory");    \
    if (!_d) {                                                                     \
        asm volatile("{\n\t.reg .pred P1;\n\tWL_%=:\n\t"                           \
            "mbarrier.try_wait.parity.acquire.cta.shared::cta.b64 P1, [%0], %1, 0x989680;\n\t" \
            "@P1 bra.uni WD_%=;\n\tbra.uni WL_%=;\n\tWD_%=:\n\t}"                  \
            :: "r"(_m), "r"(_p) : "memory");                                       \
    }                                                                              \
} while (0)

#define TCGEN05_LD_X32(regs, addr) \
    asm volatile("tcgen05.ld.sync.aligned.32x32b.x32.b32 " \
        "{%0, %1, %2, %3, %4, %5, %6, %7, %8, %9, %10, %11, %12, %13, %14, %15, " \
        " %16, %17, %18, %19, %20, %21, %22, %23, %24, %25, %26, %27, %28, %29, %30, %31}, [%32];" \
        : "=r"((regs)[0]),  "=r"((regs)[1]),  "=r"((regs)[2]),  "=r"((regs)[3]), \
          "=r"((regs)[4]),  "=r"((regs)[5]),  "=r"((regs)[6]),  "=r"((regs)[7]), \
          "=r"((regs)[8]),  "=r"((regs)[9]),  "=r"((regs)[10]), "=r"((regs)[11]), \
          "=r"((regs)[12]), "=r"((regs)[13]), "=r"((regs)[14]), "=r"((regs)[15]), \
          "=r"((regs)[16]), "=r"((regs)[17]), "=r"((regs)[18]), "=r"((regs)[19]), \
          "=r"((regs)[20]), "=r"((regs)[21]), "=r"((regs)[22]), "=r"((regs)[23]), \
          "=r"((regs)[24]), "=r"((regs)[25]), "=r"((regs)[26]), "=r"((regs)[27]), \
          "=r"((regs)[28]), "=r"((regs)[29]), "=r"((regs)[30]), "=r"((regs)[31]) \
        : "r"(addr))

// idesc: dtype F32 (1<<4), a/b BF16 (1<<7|1<<10), N=128 (16<<17), M=128 (8<<24)
#define MMA_IDESC 0x8200490u

// smem layout shared by both MMA kernels
#define SC_A0 0
#define SC_A1 (16 * 1024)
#define SC_B0 (32 * 1024)
#define SC_B1 (96 * 1024)
#define SC_CTRL (160 * 1024)       // +0 tmem ptr, +8 mbar0, +16 mbar1
#define SC_SMEM (160 * 1024 + 64)

// ========== kernel: tensor-core projection + fused split ==========
// Per CTA: 128 rows, all 512 output cols (TMEM D = 4x128). K = 6 pairings x
// 16 chunks of 64 = 96 chunks. Epilogue splits fp32 proj -> g_ps directly.
__global__ __launch_bounds__(256) void proj_mma() {
#ifdef HAS_TCGEN05
    extern __shared__ char smem[];
    const uint32_t sb = smem_to_u32(smem);
    const int tid = threadIdx.x;
    const int wid = tid >> 5;
    const int row0 = blockIdx.x * 128;

    if (wid == 0)
        asm volatile("tcgen05.alloc.cta_group::1.sync.aligned.shared::cta.b32 [%0], %1;"
                     :: "r"(sb + SC_CTRL), "r"(512u) : "memory");
    __syncthreads();
    uint32_t tmem;
    asm volatile("ld.shared.b32 %0, [%1];" : "=r"(tmem) : "r"(sb + SC_CTRL));
    if (tid == 0) {
        MBARRIER_INIT(sb + SC_CTRL + 8, 1);
        MBARRIER_INIT(sb + SC_CTRL + 16, 1);
    }
    __syncthreads();

    const int a_idx[6] = { 0, 0, 1, 0, 1, 2 };
    const int b_idx[6] = { 0, 1, 0, 2, 1, 0 };
    int ph[2] = { 0, 0 }, pend[2] = { 0, 0 };

    for (int kc = 0; kc < 96; kc++) {
        const int buf = kc & 1;
        if (pend[buf]) {
            MBARRIER_WAIT_PARITY(sb + SC_CTRL + 8 + 8 * buf, ph[buf]);
            ph[buf] ^= 1; pend[buf] = 0;
        }
        const int t = kc >> 4, koff = (kc & 15) * 64;
        const __nv_bfloat16* Asrc = g_xs  + (size_t)a_idx[t] * M_ROWS * D_DIM;
        const __nv_bfloat16* Bsrc = g_rps + (size_t)b_idx[t] * E_DIM  * D_DIM;
        const int aoff = buf ? SC_A1 : SC_A0;
        const int boff = buf ? SC_B1 : SC_B0;
        #pragma unroll
        for (int r = 0; r < 4; r++) {   // A: 128 rows x 64 bf16, SW128
            int ci = tid + 256 * r, m = ci >> 3, c8 = ci & 7;
            uint4 v = *(const uint4*)(Asrc + (size_t)(row0 + m) * D_DIM + koff + c8 * 8);
            *(uint4*)(smem + aoff + SMEM_SWIZZLE_128B(m * 128 + c8 * 16)) = v;
        }
        #pragma unroll
        for (int r = 0; r < 16; r++) {  // B: 512 N-rows x 64 bf16
            int ci = tid + 256 * r, n = ci >> 3, c8 = ci & 7;
            uint4 v = *(const uint4*)(Bsrc + (size_t)n * D_DIM + koff + c8 * 8);
            *(uint4*)(smem + boff + SMEM_SWIZZLE_128B(n * 128 + c8 * 16)) = v;
        }
        asm volatile("fence.proxy.async.shared::cta;" ::: "memory");
        __syncthreads();
        if (wid == 0 && elect_one_pred()) {
            unsigned long long ad = MAKE_SMEM_DESC(sb + aoff);
            #pragma unroll
            for (int nt = 0; nt < 4; nt++) {
                unsigned long long bd = MAKE_SMEM_DESC(sb + boff + nt * 16384);
                #pragma unroll
                for (int ks = 0; ks < 4; ks++) {
                    uint32_t en = (kc != 0 || ks != 0) ? 1u : 0u;
                    asm volatile("{\n\t.reg .pred p;\n\tsetp.ne.u32 p, %4, 0;\n\t"
                        "tcgen05.mma.cta_group::1.kind::f16 [%0], %1, %2, %3, {%5, %5, %5, %5}, p;\n\t}"
                        :: "r"(tmem + nt * 128), "l"(ad + ks * 2), "l"(bd + ks * 2),
                           "r"(MMA_IDESC), "r"(en), "r"(0u) : "memory");
                }
            }
            asm volatile("tcgen05.commit.cta_group::1.mbarrier::arrive::one.shared::cluster.b64 [%0];"
                         :: "r"(sb + SC_CTRL + 8 + 8 * buf) : "memory");
        }
        pend[buf] = 1;
        __syncthreads();
    }
    #pragma unroll
    for (int b = 0; b < 2; b++)
        if (pend[b]) {
            MBARRIER_WAIT_PARITY(sb + SC_CTRL + 8 + 8 * b, ph[b]);
            ph[b] ^= 1; pend[b] = 0;
        }
    asm volatile("tcgen05.fence::after_thread_sync;" ::: "memory");

    if (tid < 128) {   // warps 0-3, lane -> row (row = row0 + tid)
        const size_t rbase = (size_t)(row0 + tid) * E_DIM;
        #pragma unroll
        for (int nt = 0; nt < 4; nt++) {
            #pragma unroll
            for (int b4 = 0; b4 < 4; b4++) {
                uint32_t regs[32];
                TCGEN05_LD_X32(regs, tmem + nt * 128 + b4 * 32);
                asm volatile("tcgen05.wait::ld.sync.aligned;" ::: "memory");
                const int cbase = nt * 128 + b4 * 32;
                #pragma unroll
                for (int c = 0; c < 32; c += 2) {
                    __nv_bfloat16 h0[3], h1[3];
                    split3(__uint_as_float(regs[c]),     h0[0], h0[1], h0[2]);
                    split3(__uint_as_float(regs[c + 1]), h1[0], h1[1], h1[2]);
                    #pragma unroll
                    for (int s = 0; s < 3; s++) {
                        __nv_bfloat16 pr[2] = { h0[s], h1[s] };
                        *(uint32_t*)(g_ps + (size_t)s * M_ROWS * E_DIM + rbase + cbase + c)
                            = *(uint32_t*)pr;
                    }
                }
            }
        }
        asm volatile("tcgen05.fence::before_thread_sync;" ::: "memory");
    }
    __syncthreads();
    if (wid == 0)
        asm volatile("tcgen05.dealloc.cta_group::1.sync.aligned.b32 %0, %1;" :: "r"(tmem), "r"(512u));
#endif
}

// ========== kernel: tensor-core score + argmax (R12 verbatim) ==========
__global__ __launch_bounds__(256) void score_mma(float* __restrict__ out) {
#ifdef HAS_TCGEN05
    extern __shared__ char smem[];
    const uint32_t sb = smem_to_u32(smem);
    const int tid = threadIdx.x;
    const int wid = tid >> 5;
    const int row0 = blockIdx.x * 128;

    if (wid == 0)
        asm volatile("tcgen05.alloc.cta_group::1.sync.aligned.shared::cta.b32 [%0], %1;"
                     :: "r"(sb + SC_CTRL), "r"(512u) : "memory");
    __syncthreads();
    uint32_t tmem;
    asm volatile("ld.shared.b32 %0, [%1];" : "=r"(tmem) : "r"(sb + SC_CTRL));
    if (tid == 0) {
        MBARRIER_INIT(sb + SC_CTRL + 8, 1);
        MBARRIER_INIT(sb + SC_CTRL + 16, 1);
    }
    __syncthreads();

    const int a_idx[6] = { 0, 0, 1, 0, 1, 2 };
    const int b_idx[6] = { 0, 1, 0, 2, 1, 0 };

    float best = -3.402823466e38f;
    int besti = 0;
    int ph[2] = { 0, 0 }, pend[2] = { 0, 0 };

    for (int g = 0; g < 8; g++) {
        for (int kc = 0; kc < 48; kc++) {
            const int gc = g * 48 + kc;
            const int buf = gc & 1;
            if (pend[buf]) {
                MBARRIER_WAIT_PARITY(sb + SC_CTRL + 8 + 8 * buf, ph[buf]);
                ph[buf] ^= 1; pend[buf] = 0;
            }
            const int t = kc >> 3, koff = (kc & 7) * 64;
            const __nv_bfloat16* Asrc = g_ps  + (size_t)a_idx[t] * M_ROWS * E_DIM;
            const __nv_bfloat16* Bsrc = g_cbs + (size_t)b_idx[t] * C_DIM  * E_DIM;
            const int aoff = buf ? SC_A1 : SC_A0;
            const int boff = buf ? SC_B1 : SC_B0;
            #pragma unroll
            for (int r = 0; r < 4; r++) {
                int ci = tid + 256 * r, m = ci >> 3, c8 = ci & 7;
                uint4 v = *(const uint4*)(Asrc + (size_t)(row0 + m) * E_DIM + koff + c8 * 8);
                *(uint4*)(smem + aoff + SMEM_SWIZZLE_128B(m * 128 + c8 * 16)) = v;
            }
            #pragma unroll
            for (int r = 0; r < 16; r++) {
                int ci = tid + 256 * r, n = ci >> 3, c8 = ci & 7;
                uint4 v = *(const uint4*)(Bsrc + (size_t)(g * 512 + n) * E_DIM + koff + c8 * 8);
                *(uint4*)(smem + boff + SMEM_SWIZZLE_128B(n * 128 + c8 * 16)) = v;
            }
            asm volatile("fence.proxy.async.shared::cta;" ::: "memory");
            __syncthreads();
            if (wid == 0 && elect_one_pred()) {
                unsigned long long ad = MAKE_SMEM_DESC(sb + aoff);
                #pragma unroll
                for (int nt = 0; nt < 4; nt++) {
                    unsigned long long bd = MAKE_SMEM_DESC(sb + boff + nt * 16384);
                    #pragma unroll
                    for (int ks = 0; ks < 4; ks++) {
                        uint32_t en = (kc != 0 || ks != 0) ? 1u : 0u;
                        asm volatile("{\n\t.reg .pred p;\n\tsetp.ne.u32 p, %4, 0;\n\t"
                            "tcgen05.mma.cta_group::1.kind::f16 [%0], %1, %2, %3, {%5, %5, %5, %5}, p;\n\t}"
                            :: "r"(tmem + nt * 128), "l"(ad + ks * 2), "l"(bd + ks * 2),
                               "r"(MMA_IDESC), "r"(en), "r"(0u) : "memory");
                    }
                }
                asm volatile("tcgen05.commit.cta_group::1.mbarrier::arrive::one.shared::cluster.b64 [%0];"
                             :: "r"(sb + SC_CTRL + 8 + 8 * buf) : "memory");
            }
            pend[buf] = 1;
            __syncthreads();
        }
        #pragma unroll
        for (int b = 0; b < 2; b++)
            if (pend[b]) {
                MBARRIER_WAIT_PARITY(sb + SC_CTRL + 8 + 8 * b, ph[b]);
                ph[b] ^= 1; pend[b] = 0;
            }
        asm volatile("tcgen05.fence::after_thread_sync;" ::: "memory");
        if (tid < 128) {
            #pragma unroll
            for (int nt = 0; nt < 4; nt++) {
                #pragma unroll
                for (int b4 = 0; b4 < 4; b4++) {
                    uint32_t regs[32];
                    TCGEN05_LD_X32(regs, tmem + nt * 128 + b4 * 32);
                    asm volatile("tcgen05.wait::ld.sync.aligned;" ::: "memory");
                    const int cbase = g * 512 + nt * 128 + b4 * 32;
                    #pragma unroll
                    for (int c = 0; c < 32; c++) {
                        float s = __uint_as_float(regs[c]);
                        if (s > best) { best = s; besti = cbase + c; }
                    }
                }
            }
            asm volatile("tcgen05.fence::before_thread_sync;" ::: "memory");
        }
        __syncthreads();
    }

    if (tid < 128) out[row0 + tid] = (float)besti;   // harness reads float32
    __syncthreads();
    if (wid == 0)
        asm volatile("tcgen05.dealloc.cta_group::1.sync.aligned.b32 %0, %1;" :: "r"(tmem), "r"(512u));
#endif
}

extern "C" void kernel_launch(void* const* d_in, const int* in_sizes, int n_in,
                              void* d_out, int out_size) {
    const float* x  = nullptr;
    const float* rp = nullptr;
    const float* cb = nullptr;
    for (int i = 0; i < n_in; i++) {
        if (in_sizes[i] == X_ELEMS)       x  = (const float*)d_in[i];
        else if (in_sizes[i] == RP_ELEMS) rp = (const float*)d_in[i];
        else if (in_sizes[i] == CB_ELEMS) cb = (const float*)d_in[i];
    }
    if (!x || !rp || !cb) {
        x  = (const float*)d_in[0];
        rp = (const float*)d_in[1];
        cb = (const float*)d_in[2];
    }
    float* out = (float*)d_out;  // harness reads output as float32

    cudaFuncSetAttribute(proj_mma,  cudaFuncAttributeMaxDynamicSharedMemorySize, SC_SMEM);
    cudaFuncSetAttribute(score_mma, cudaFuncAttributeMaxDynamicSharedMemorySize, SC_SMEM);

    split_x<<<(M_ROWS * D_DIM) / 1024, 256>>>(x);
    split_rpt<<<dim3(E_DIM / 32, D_DIM / 32), dim3(32, 8)>>>(rp);
    split_cbn<<<C_DIM, 128>>>(cb);
    proj_mma<<<M_ROWS / 128, 256, SC_SMEM>>>();
    score_mma<<<M_ROWS / 128, 256, SC_SMEM>>>(out);
}

// round 15
// speedup vs baseline: 5.2783x; 1.9695x over previous
#include <cuda_runtime.h>
#include <cuda_bf16.h>
#include <cstdint>

// Dims (fixed): B=8, N=4096 -> M=32768; D=1024; E=512; C=4096
#define M_ROWS 32768
#define D_DIM  1024
#define E_DIM  512
#define C_DIM  4096

#define X_ELEMS  (M_ROWS * D_DIM)   // 33554432
#define RP_ELEMS (D_DIM * E_DIM)    // 524288
#define CB_ELEMS (C_DIM * E_DIM)    // 2097152

// Scratch (device globals: allocation-free per harness rules).
__device__ __align__(256) __nv_bfloat16  g_xs[(size_t)3 * M_ROWS * D_DIM];  // 192 MB x splits [M][D]
__device__ __align__(256) __nv_bfloat16  g_rps[(size_t)3 * E_DIM * D_DIM]; //   3 MB RP^T splits [N][K]
__device__ __align__(256) __nv_bfloat16  g_ps[(size_t)3 * M_ROWS * E_DIM]; //  96 MB proj splits [M][E]
__device__ __align__(256) __nv_bfloat16  g_cbs[(size_t)3 * C_DIM * E_DIM]; //  12 MB normalized-cb splits

// Arch-specific gate: tcgen05 exists only on sm_103a-style targets.
#if defined(__CUDA_ARCH_FEAT_SM103_ALL)
#define HAS_TCGEN05 1
#elif defined(__CUDA_ARCH_SPECIFIC__)
#if __CUDA_ARCH_SPECIFIC__ == 1030
#define HAS_TCGEN05 1
#endif
#endif

// fp32 -> 3 exact-residual bf16 splits
__device__ __forceinline__ void split3(float v, __nv_bfloat16& b1, __nv_bfloat16& b2, __nv_bfloat16& b3) {
    b1 = __float2bfloat16(v);
    float r = v - __bfloat162float(b1);
    b2 = __float2bfloat16(r);
    b3 = __float2bfloat16(r - __bfloat162float(b2));
}

// ========== prep kernels (unchanged, verified) ==========
__global__ void split_x(const float* __restrict__ x) {
    const size_t i = ((size_t)blockIdx.x * blockDim.x + threadIdx.x) * 4;
    float4 v = *(const float4*)(x + i);
    float a[4] = { v.x, v.y, v.z, v.w };
    __nv_bfloat16 h[3][4];
    #pragma unroll
    for (int j = 0; j < 4; j++) split3(a[j], h[0][j], h[1][j], h[2][j]);
    #pragma unroll
    for (int s = 0; s < 3; s++)
        *(uint2*)(g_xs + (size_t)s * M_ROWS * D_DIM + i) = *(uint2*)h[s];
}

__global__ void split_rpt(const float* __restrict__ rp) {
    __shared__ float t[32][33];
    const int tx = threadIdx.x, ty = threadIdx.y;       // 32 x 8
    const int n0 = blockIdx.x * 32, k0 = blockIdx.y * 32;
    #pragma unroll
    for (int i = 0; i < 4; i++)
        t[ty + 8 * i][tx] = rp[(size_t)(k0 + ty + 8 * i) * E_DIM + n0 + tx];
    __syncthreads();
    #pragma unroll
    for (int i = 0; i < 4; i++) {
        float v = t[tx][ty + 8 * i];
        __nv_bfloat16 b1, b2, b3;
        split3(v, b1, b2, b3);
        const size_t o = (size_t)(n0 + ty + 8 * i) * D_DIM + k0 + tx;
        g_rps[o] = b1;
        g_rps[(size_t)E_DIM * D_DIM + o] = b2;
        g_rps[2 * (size_t)E_DIM * D_DIM + o] = b3;
    }
}

__global__ void split_cbn(const float* __restrict__ cb) {
    __shared__ float red[4];
    const int c = blockIdx.x, t = threadIdx.x;   // 128 threads
    const float* v = cb + (size_t)c * E_DIM;
    float4 x = *(const float4*)(v + t * 4);
    float ss = x.x * x.x + x.y * x.y + x.z * x.z + x.w * x.w;
    #pragma unroll
    for (int o = 16; o > 0; o >>= 1) ss += __shfl_xor_sync(0xffffffffu, ss, o);
    if ((t & 31) == 0) red[t >> 5] = ss;
    __syncthreads();
    const float inv = 1.f / fmaxf(sqrtf(red[0] + red[1] + red[2] + red[3]), 1e-12f);
    float a[4] = { x.x * inv, x.y * inv, x.z * inv, x.w * inv };
    __nv_bfloat16 h[3][4];
    #pragma unroll
    for (int j = 0; j < 4; j++) split3(a[j], h[0][j], h[1][j], h[2][j]);
    const size_t base = (size_t)c * E_DIM + t * 4;
    #pragma unroll
    for (int s = 0; s < 3; s++)
        *(uint2*)(g_cbs + (size_t)s * C_DIM * E_DIM + base) = *(uint2*)h[s];
}

// ================= tcgen05 / async PTX helpers ================
__device__ __forceinline__ uint32_t elect_one_pred() {
    uint32_t pred;
    asm volatile("{\n\t.reg .pred p;\n\telect.sync _|p, 0xFFFFFFFF;\n\t"
                 "selp.b32 %0, 1, 0, p;\n\t}" : "=r"(pred));
    return pred;
}
__device__ __forceinline__ uint32_t smem_to_u32(const void* p) {
    uint32_t a;
    asm("{ .reg .u64 t; cvta.to.shared.u64 t, %1; cvt.u32.u64 %0, t; }" : "=r"(a) : "l"(p));
    return a;
}
__device__ __forceinline__ void cp16(uint32_t dst, const void* src) {
    asm volatile("cp.async.cg.shared.global [%0], [%1], 16;" :: "r"(dst), "l"(src));
}
#define CP_COMMIT()  asm volatile("cp.async.commit_group;" ::: "memory")
#define CP_WAIT_1()  asm volatile("cp.async.wait_group 1;" ::: "memory")
#define CP_WAIT_0()  asm volatile("cp.async.wait_group 0;" ::: "memory")

#define SMEM_SWIZZLE_128B(off) ((off) ^ (((off) >> 3) & 0x70))
static constexpr unsigned long long SMEM_DESC_BASE_SW128 =
    (2ull << 61) | (1ull << 46) | (64ull << 32) | (1ull << 16);
#define MAKE_SMEM_DESC(a) (SMEM_DESC_BASE_SW128 | ((unsigned long long)((a) >> 4) & 0x3FFF))

#define MBARRIER_INIT(mb, n) \
    asm volatile("mbarrier.init.shared.b64 [%0], %1;" :: "r"((uint32_t)(mb)), "r"((uint32_t)(n)) : "memory")
#define MBARRIER_WAIT_PARITY(mb, par) do {                                        \
    uint32_t _m = (uint32_t)(mb), _p = (uint32_t)(par), _d;                        \
    asm volatile("{\n\t.reg .pred p;\n\t"                                          \
        "mbarrier.try_wait.parity.acquire.cta.shared::cta.b64 p, [%1], %2;\n\t"    \
        "selp.b32 %0, 1, 0, p;\n\t}" : "=r"(_d) : "r"(_m), "r"(_p) : "memory");    \
    if (!_d) {                                                                     \
        asm volatile("{\n\t.reg .pred P1;\n\tWL_%=:\n\t"                           \
            "mbarrier.try_wait.parity.acquire.cta.shared::cta.b64 P1, [%0], %1, 0x989680;\n\t" \
            "@P1 bra.uni WD_%=;\n\tbra.uni WL_%=;\n\tWD_%=:\n\t}"                  \
            :: "r"(_m), "r"(_p) : "memory");                                       \
    }                                                                              \
} while (0)

#define TCGEN05_LD_X32(regs, addr) \
    asm volatile("tcgen05.ld.sync.aligned.32x32b.x32.b32 " \
        "{%0, %1, %2, %3, %4, %5, %6, %7, %8, %9, %10, %11, %12, %13, %14, %15, " \
        " %16, %17, %18, %19, %20, %21, %22, %23, %24, %25, %26, %27, %28, %29, %30, %31}, [%32];" \
        : "=r"((regs)[0]),  "=r"((regs)[1]),  "=r"((regs)[2]),  "=r"((regs)[3]), \
          "=r"((regs)[4]),  "=r"((regs)[5]),  "=r"((regs)[6]),  "=r"((regs)[7]), \
          "=r"((regs)[8]),  "=r"((regs)[9]),  "=r"((regs)[10]), "=r"((regs)[11]), \
          "=r"((regs)[12]), "=r"((regs)[13]), "=r"((regs)[14]), "=r"((regs)[15]), \
          "=r"((regs)[16]), "=r"((regs)[17]), "=r"((regs)[18]), "=r"((regs)[19]), \
          "=r"((regs)[20]), "=r"((regs)[21]), "=r"((regs)[22]), "=r"((regs)[23]), \
          "=r"((regs)[24]), "=r"((regs)[25]), "=r"((regs)[26]), "=r"((regs)[27]), \
          "=r"((regs)[28]), "=r"((regs)[29]), "=r"((regs)[30]), "=r"((regs)[31]) \
        : "r"(addr))

// idesc: dtype F32 (1<<4), a/b BF16 (1<<7|1<<10), N=128 (16<<17), M=128 (8<<24)
#define MMA_IDESC 0x8200490u

#define SC_A0 0
#define SC_A1 (16 * 1024)
#define SC_B0 (32 * 1024)
#define SC_B1 (96 * 1024)
#define SC_CTRL (160 * 1024)       // +0 tmem ptr, +8 mbar0, +16 mbar1
#define SC_SMEM (160 * 1024 + 64)

#ifdef HAS_TCGEN05
// issue the 16 MMAs for one 64-K chunk (warp0 elect thread only)
__device__ __forceinline__ void issue_chunk_mmas(uint32_t tmem, uint32_t sb,
                                                 int aoff, int boff, bool first_chunk) {
    unsigned long long ad = MAKE_SMEM_DESC(sb + aoff);
    #pragma unroll
    for (int nt = 0; nt < 4; nt++) {
        unsigned long long bd = MAKE_SMEM_DESC(sb + boff + nt * 16384);
        #pragma unroll
        for (int ks = 0; ks < 4; ks++) {
            uint32_t en = (!first_chunk || ks != 0) ? 1u : 0u;
            asm volatile("{\n\t.reg .pred p;\n\tsetp.ne.u32 p, %4, 0;\n\t"
                "tcgen05.mma.cta_group::1.kind::f16 [%0], %1, %2, %3, {%5, %5, %5, %5}, p;\n\t}"
                :: "r"(tmem + nt * 128), "l"(ad + ks * 2), "l"(bd + ks * 2),
                   "r"(MMA_IDESC), "r"(en), "r"(0u) : "memory");
        }
    }
}
#endif

// ========== kernel: tensor-core projection + fused split (pipelined) ==========
__global__ __launch_bounds__(256) void proj_mma() {
#ifdef HAS_TCGEN05
    extern __shared__ char smem[];
    const uint32_t sb = smem_to_u32(smem);
    const int tid = threadIdx.x;
    const int wid = tid >> 5;
    const int row0 = blockIdx.x * 128;

    if (wid == 0)
        asm volatile("tcgen05.alloc.cta_group::1.sync.aligned.shared::cta.b32 [%0], %1;"
                     :: "r"(sb + SC_CTRL), "r"(512u) : "memory");
    __syncthreads();
    uint32_t tmem;
    asm volatile("ld.shared.b32 %0, [%1];" : "=r"(tmem) : "r"(sb + SC_CTRL));
    if (tid == 0) {
        MBARRIER_INIT(sb + SC_CTRL + 8, 1);
        MBARRIER_INIT(sb + SC_CTRL + 16, 1);
    }
    __syncthreads();

    const int a_idx[6] = { 0, 0, 1, 0, 1, 2 };
    const int b_idx[6] = { 0, 1, 0, 2, 1, 0 };

    auto fill = [&](int buf, int kc) {
        const int t = kc >> 4, koff = (kc & 15) * 64;
        const __nv_bfloat16* Asrc = g_xs  + (size_t)a_idx[t] * M_ROWS * D_DIM;
        const __nv_bfloat16* Bsrc = g_rps + (size_t)b_idx[t] * E_DIM  * D_DIM;
        const int aoff = buf ? SC_A1 : SC_A0;
        const int boff = buf ? SC_B1 : SC_B0;
        #pragma unroll
        for (int r = 0; r < 4; r++) {
            int ci = tid + 256 * r, m = ci >> 3, c8 = ci & 7;
            cp16(sb + aoff + SMEM_SWIZZLE_128B(m * 128 + c8 * 16),
                 Asrc + (size_t)(row0 + m) * D_DIM + koff + c8 * 8);
        }
        #pragma unroll
        for (int r = 0; r < 16; r++) {
            int ci = tid + 256 * r, n = ci >> 3, c8 = ci & 7;
            cp16(sb + boff + SMEM_SWIZZLE_128B(n * 128 + c8 * 16),
                 Bsrc + (size_t)n * D_DIM + koff + c8 * 8);
        }
    };

    int ph[2] = { 0, 0 }, pend[2] = { 0, 0 };
    fill(0, 0); CP_COMMIT();

    for (int kc = 0; kc < 96; kc++) {
        const int buf = kc & 1;
        if (kc + 1 < 96) {
            const int nb = buf ^ 1;
            if (pend[nb]) {
                MBARRIER_WAIT_PARITY(sb + SC_CTRL + 8 + 8 * nb, ph[nb]);
                ph[nb] ^= 1; pend[nb] = 0;
            }
            fill(nb, kc + 1); CP_COMMIT();
            CP_WAIT_1();
        } else {
            CP_WAIT_0();
        }
        asm volatile("fence.proxy.async.shared::cta;" ::: "memory");
        __syncthreads();
        if (wid == 0 && elect_one_pred()) {
            issue_chunk_mmas(tmem, sb, buf ? SC_A1 : SC_A0, buf ? SC_B1 : SC_B0, kc == 0);
            asm volatile("tcgen05.commit.cta_group::1.mbarrier::arrive::one.shared::cluster.b64 [%0];"
                         :: "r"(sb + SC_CTRL + 8 + 8 * buf) : "memory");
        }
        pend[buf] = 1;
    }
    #pragma unroll
    for (int b = 0; b < 2; b++)
        if (pend[b]) {
            MBARRIER_WAIT_PARITY(sb + SC_CTRL + 8 + 8 * b, ph[b]);
            ph[b] ^= 1; pend[b] = 0;
        }
    asm volatile("tcgen05.fence::after_thread_sync;" ::: "memory");

    if (tid < 128) {   // warps 0-3, lane -> row (row = row0 + tid)
        const size_t rbase = (size_t)(row0 + tid) * E_DIM;
        #pragma unroll
        for (int nt = 0; nt < 4; nt++) {
            #pragma unroll
            for (int b4 = 0; b4 < 4; b4++) {
                uint32_t regs[32];
                TCGEN05_LD_X32(regs, tmem + nt * 128 + b4 * 32);
                asm volatile("tcgen05.wait::ld.sync.aligned;" ::: "memory");
                const int cbase = nt * 128 + b4 * 32;
                #pragma unroll
                for (int c = 0; c < 32; c += 2) {
                    __nv_bfloat16 h0[3], h1[3];
                    split3(__uint_as_float(regs[c]),     h0[0], h0[1], h0[2]);
                    split3(__uint_as_float(regs[c + 1]), h1[0], h1[1], h1[2]);
                    #pragma unroll
                    for (int s = 0; s < 3; s++) {
                        __nv_bfloat16 pr[2] = { h0[s], h1[s] };
                        *(uint32_t*)(g_ps + (size_t)s * M_ROWS * E_DIM + rbase + cbase + c)
                            = *(uint32_t*)pr;
                    }
                }
            }
        }
        asm volatile("tcgen05.fence::before_thread_sync;" ::: "memory");
    }
    __syncthreads();
    if (wid == 0)
        asm volatile("tcgen05.dealloc.cta_group::1.sync.aligned.b32 %0, %1;" :: "r"(tmem), "r"(512u));
#endif
}

// ========== kernel: tensor-core score + argmax (pipelined) ==========
__global__ __launch_bounds__(256) void score_mma(float* __restrict__ out) {
#ifdef HAS_TCGEN05
    extern __shared__ char smem[];
    const uint32_t sb = smem_to_u32(smem);
    const int tid = threadIdx.x;
    const int wid = tid >> 5;
    const int row0 = blockIdx.x * 128;

    if (wid == 0)
        asm volatile("tcgen05.alloc.cta_group::1.sync.aligned.shared::cta.b32 [%0], %1;"
                     :: "r"(sb + SC_CTRL), "r"(512u) : "memory");
    __syncthreads();
    uint32_t tmem;
    asm volatile("ld.shared.b32 %0, [%1];" : "=r"(tmem) : "r"(sb + SC_CTRL));
    if (tid == 0) {
        MBARRIER_INIT(sb + SC_CTRL + 8, 1);
        MBARRIER_INIT(sb + SC_CTRL + 16, 1);
    }
    __syncthreads();

    const int a_idx[6] = { 0, 0, 1, 0, 1, 2 };
    const int b_idx[6] = { 0, 1, 0, 2, 1, 0 };

    auto fill = [&](int buf, int gc) {
        const int kc = gc % 48, g = gc / 48;
        const int t = kc >> 3, koff = (kc & 7) * 64;
        const __nv_bfloat16* Asrc = g_ps  + (size_t)a_idx[t] * M_ROWS * E_DIM;
        const __nv_bfloat16* Bsrc = g_cbs + (size_t)b_idx[t] * C_DIM  * E_DIM;
        const int aoff = buf ? SC_A1 : SC_A0;
        const int boff = buf ? SC_B1 : SC_B0;
        #pragma unroll
        for (int r = 0; r < 4; r++) {
            int ci = tid + 256 * r, m = ci >> 3, c8 = ci & 7;
            cp16(sb + aoff + SMEM_SWIZZLE_128B(m * 128 + c8 * 16),
                 Asrc + (size_t)(row0 + m) * E_DIM + koff + c8 * 8);
        }
        #pragma unroll
        for (int r = 0; r < 16; r++) {
            int ci = tid + 256 * r, n = ci >> 3, c8 = ci & 7;
            cp16(sb + boff + SMEM_SWIZZLE_128B(n * 128 + c8 * 16),
                 Bsrc + (size_t)(g * 512 + n) * E_DIM + koff + c8 * 8);
        }
    };

    float best = -3.402823466e38f;
    int besti = 0;
    int ph[2] = { 0, 0 }, pend[2] = { 0, 0 };

    fill(0, 0); CP_COMMIT();

    for (int gc = 0; gc < 384; gc++) {
        const int buf = gc & 1;
        if (gc + 1 < 384) {
            const int nb = buf ^ 1;
            if (pend[nb]) {
                MBARRIER_WAIT_PARITY(sb + SC_CTRL + 8 + 8 * nb, ph[nb]);
                ph[nb] ^= 1; pend[nb] = 0;
            }
            fill(nb, gc + 1); CP_COMMIT();
            CP_WAIT_1();
        } else {
            CP_WAIT_0();
        }
        asm volatile("fence.proxy.async.shared::cta;" ::: "memory");
        __syncthreads();
        if (wid == 0 && elect_one_pred()) {
            issue_chunk_mmas(tmem, sb, buf ? SC_A1 : SC_A0, buf ? SC_B1 : SC_B0, (gc % 48) == 0);
            asm volatile("tcgen05.commit.cta_group::1.mbarrier::arrive::one.shared::cluster.b64 [%0];"
                         :: "r"(sb + SC_CTRL + 8 + 8 * buf) : "memory");
        }
        pend[buf] = 1;

        if ((gc % 48) == 47) {
            // end of C-group: drain, read D, update argmax (ascending c ->
            // strict > keeps FIRST max, matching jnp.argmax)
            #pragma unroll
            for (int b = 0; b < 2; b++)
                if (pend[b]) {
                    MBARRIER_WAIT_PARITY(sb + SC_CTRL + 8 + 8 * b, ph[b]);
                    ph[b] ^= 1; pend[b] = 0;
                }
            asm volatile("tcgen05.fence::after_thread_sync;" ::: "memory");
            const int g = gc / 48;
            if (tid < 128) {
                #pragma unroll
                for (int nt = 0; nt < 4; nt++) {
                    #pragma unroll
                    for (int b4 = 0; b4 < 4; b4++) {
                        uint32_t regs[32];
                        TCGEN05_LD_X32(regs, tmem + nt * 128 + b4 * 32);
                        asm volatile("tcgen05.wait::ld.sync.aligned;" ::: "memory");
                        const int cbase = g * 512 + nt * 128 + b4 * 32;
                        #pragma unroll
                        for (int c = 0; c < 32; c++) {
                            float s = __uint_as_float(regs[c]);
                            if (s > best) { best = s; besti = cbase + c; }
                        }
                    }
                }
                asm volatile("tcgen05.fence::before_thread_sync;" ::: "memory");
            }
            __syncthreads();
        }
    }

    if (tid < 128) out[row0 + tid] = (float)besti;   // harness reads float32
    __syncthreads();
    if (wid == 0)
        asm volatile("tcgen05.dealloc.cta_group::1.sync.aligned.b32 %0, %1;" :: "r"(tmem), "r"(512u));
#endif
}

extern "C" void kernel_launch(void* const* d_in, const int* in_sizes, int n_in,
                              void* d_out, int out_size) {
    const float* x  = nullptr;
    const float* rp = nullptr;
    const float* cb = nullptr;
    for (int i = 0; i < n_in; i++) {
        if (in_sizes[i] == X_ELEMS)       x  = (const float*)d_in[i];
        else if (in_sizes[i] == RP_ELEMS) rp = (const float*)d_in[i];
        else if (in_sizes[i] == CB_ELEMS) cb = (const float*)d_in[i];
    }
    if (!x || !rp || !cb) {
        x  = (const float*)d_in[0];
        rp = (const float*)d_in[1];
        cb = (const float*)d_in[2];
    }
    float* out = (float*)d_out;  // harness reads output as float32

    cudaFuncSetAttribute(proj_mma,  cudaFuncAttributeMaxDynamicSharedMemorySize, SC_SMEM);
    cudaFuncSetAttribute(score_mma, cudaFuncAttributeMaxDynamicSharedMemorySize, SC_SMEM);

    split_x<<<(M_ROWS * D_DIM) / 1024, 256>>>(x);
    split_rpt<<<dim3(E_DIM / 32, D_DIM / 32), dim3(32, 8)>>>(rp);
    split_cbn<<<C_DIM, 128>>>(cb);
    proj_mma<<<M_ROWS / 128, 256, SC_SMEM>>>();
    score_mma<<<M_ROWS / 128, 256, SC_SMEM>>>(out);
}